// round 1
// baseline (speedup 1.0000x reference)
#include <cuda_runtime.h>
#include <math_constants.h>

#define TDIM   1024
#define DDIM   1024
#define NBATCH 8
#define NHEADS 16
#define HDIM   64
#define MROWS  (NBATCH * TDIM)   // 8192

// Scratch (allocation-free rule: __device__ globals)
__device__ float g_q[MROWS * DDIM];
__device__ float g_k[MROWS * DDIM];
__device__ float g_v[MROWS * DDIM];
__device__ float g_att[MROWS * DDIM];

// ---------------------------------------------------------------------------
// NT SGEMM body: C[m][n] = sum_k A[m][k] * B[n][k]
// M=8192 (grid.y=64), N=1024 (grid.x=8), K=1024. 128x128x8 tiles, 256 thr,
// 8x8 per thread, double-buffered smem (1 sync/iter), prefetch in regs.
// ---------------------------------------------------------------------------
__device__ __forceinline__ void gemm_nt_body(const float* __restrict__ A,
                                             const float* __restrict__ B,
                                             float* __restrict__ C)
{
    __shared__ float As[2][8][132];   // pad 132 to dodge store conflicts, keeps 16B align
    __shared__ float Bs[2][8][132];

    const int tid = threadIdx.x;
    const int m0  = blockIdx.y * 128;
    const int n0  = blockIdx.x * 128;
    const int lr  = tid >> 1;          // 0..127 tile row for loads
    const int lc  = (tid & 1) * 4;     // 0 or 4 within BK=8
    const int tx  = tid & 15;
    const int ty  = tid >> 4;

    const float* Ap = A + (m0 + lr) * DDIM + lc;
    const float* Bp = B + (n0 + lr) * DDIM + lc;

    // preload tile 0
    float4 av = *(const float4*)Ap;
    float4 bv = *(const float4*)Bp;
    As[0][lc + 0][lr] = av.x; As[0][lc + 1][lr] = av.y;
    As[0][lc + 2][lr] = av.z; As[0][lc + 3][lr] = av.w;
    Bs[0][lc + 0][lr] = bv.x; Bs[0][lc + 1][lr] = bv.y;
    Bs[0][lc + 2][lr] = bv.z; Bs[0][lc + 3][lr] = bv.w;
    __syncthreads();

    float acc[8][8];
#pragma unroll
    for (int i = 0; i < 8; i++)
#pragma unroll
        for (int j = 0; j < 8; j++) acc[i][j] = 0.f;

    for (int kt = 0; kt < 128; kt++) {
        const int cur = kt & 1;
        const int nxt = cur ^ 1;
        if (kt < 127) {                 // prefetch next tile (latency hidden by FMAs)
            av = *(const float4*)(Ap + (kt + 1) * 8);
            bv = *(const float4*)(Bp + (kt + 1) * 8);
        }
#pragma unroll
        for (int kk = 0; kk < 8; kk++) {
            float a[8], b[8];
            *(float4*)(a)     = *(const float4*)&As[cur][kk][ty * 8];
            *(float4*)(a + 4) = *(const float4*)&As[cur][kk][ty * 8 + 4];
            *(float4*)(b)     = *(const float4*)&Bs[cur][kk][tx * 8];
            *(float4*)(b + 4) = *(const float4*)&Bs[cur][kk][tx * 8 + 4];
#pragma unroll
            for (int i = 0; i < 8; i++)
#pragma unroll
                for (int j = 0; j < 8; j++)
                    acc[i][j] += a[i] * b[j];
        }
        if (kt < 127) {
            As[nxt][lc + 0][lr] = av.x; As[nxt][lc + 1][lr] = av.y;
            As[nxt][lc + 2][lr] = av.z; As[nxt][lc + 3][lr] = av.w;
            Bs[nxt][lc + 0][lr] = bv.x; Bs[nxt][lc + 1][lr] = bv.y;
            Bs[nxt][lc + 2][lr] = bv.z; Bs[nxt][lc + 3][lr] = bv.w;
        }
        __syncthreads();
    }

#pragma unroll
    for (int i = 0; i < 8; i++) {
        float4* cp = (float4*)(C + (m0 + ty * 8 + i) * DDIM + n0 + tx * 8);
        cp[0] = make_float4(acc[i][0], acc[i][1], acc[i][2], acc[i][3]);
        cp[1] = make_float4(acc[i][4], acc[i][5], acc[i][6], acc[i][7]);
    }
}

// Fused QKV projection: grid.z selects which weight/output.
__global__ __launch_bounds__(256) void qkv_kernel(const float* __restrict__ x,
                                                  const float* __restrict__ Wk,
                                                  const float* __restrict__ Wq,
                                                  const float* __restrict__ Wv)
{
    if (blockIdx.z == 0)      gemm_nt_body(x, Wq, g_q);
    else if (blockIdx.z == 1) gemm_nt_body(x, Wk, g_k);
    else                      gemm_nt_body(x, Wv, g_v);
}

__global__ __launch_bounds__(256) void out_kernel(const float* __restrict__ Wo,
                                                  float* __restrict__ out)
{
    gemm_nt_body(g_att, Wo, out);
}

// ---------------------------------------------------------------------------
// Causal flash attention, fp32. One block = one (b,h) x 128 query rows.
// One thread owns one query row: q[64] and o[64] live in registers.
// K/V tiles (16 x 64) staged in smem, read as broadcast LDS.128.
// Reference semantics: mask to -inf BEFORE the 1/sqrt(64) scale (equivalent
// to scale-then-mask since -inf/8 = -inf).
// ---------------------------------------------------------------------------
__global__ __launch_bounds__(128) void attn_kernel()
{
    __shared__ float kt[16][64];
    __shared__ float vt[16][64];

    const int tid = threadIdx.x;
    const int bh  = blockIdx.x;
    const int b   = bh >> 4;
    const int h   = bh & 15;
    const int r   = blockIdx.y * 128 + tid;     // query row within T

    const float* qrow = g_q + (b * TDIM + r) * DDIM + h * HDIM;
    float q[64];
#pragma unroll
    for (int i = 0; i < 16; i++) {
        float4 t = *(const float4*)(qrow + 4 * i);
        q[4 * i] = t.x; q[4 * i + 1] = t.y; q[4 * i + 2] = t.z; q[4 * i + 3] = t.w;
    }

    float o[64];
#pragma unroll
    for (int d = 0; d < 64; d++) o[d] = 0.f;
    float mrow = -CUDART_INF_F;
    float lrow = 0.f;

    const float* kbase = g_k + b * TDIM * DDIM + h * HDIM;
    const float* vbase = g_v + b * TDIM * DDIM + h * HDIM;
    const int nkb = blockIdx.y * 8 + 8;          // key tiles of 16 covering 0..r0+127

    for (int kb = 0; kb < nkb; kb++) {
        // cooperative tile load: 2x 16B per thread, coalesced
#pragma unroll
        for (int it = 0; it < 2; it++) {
            int i   = tid * 2 + it;
            int row = i >> 4;
            int c4  = (i & 15) * 4;
            *(float4*)&kt[row][c4] = *(const float4*)(kbase + (kb * 16 + row) * DDIM + c4);
            *(float4*)&vt[row][c4] = *(const float4*)(vbase + (kb * 16 + row) * DDIM + c4);
        }
        __syncthreads();

        const int col0 = kb * 16;
        float s[16];
#pragma unroll
        for (int j = 0; j < 16; j++) {
            float a0 = 0.f, a1 = 0.f, a2 = 0.f, a3 = 0.f;
#pragma unroll
            for (int d4 = 0; d4 < 16; d4++) {
                float4 kv = *(const float4*)&kt[j][4 * d4];
                a0 += q[4 * d4]     * kv.x;
                a1 += q[4 * d4 + 1] * kv.y;
                a2 += q[4 * d4 + 2] * kv.z;
                a3 += q[4 * d4 + 3] * kv.w;
            }
            float sv = (a0 + a1) + (a2 + a3);
            s[j] = (col0 + j <= r) ? sv * 0.125f : -CUDART_INF_F;
        }

        float mnew = mrow;
#pragma unroll
        for (int j = 0; j < 16; j++) mnew = fmaxf(mnew, s[j]);

        float scale = __expf(mrow - mnew);       // 0 when mrow=-inf (first tile)
        float p[16];
        float psum = 0.f;
#pragma unroll
        for (int j = 0; j < 16; j++) { p[j] = __expf(s[j] - mnew); psum += p[j]; }

        mrow = mnew;
        lrow = lrow * scale + psum;
#pragma unroll
        for (int d = 0; d < 64; d++) o[d] *= scale;
#pragma unroll
        for (int j = 0; j < 16; j++) {
            float pj = p[j];
#pragma unroll
            for (int d4 = 0; d4 < 16; d4++) {
                float4 vv = *(const float4*)&vt[j][4 * d4];
                o[4 * d4]     += pj * vv.x;
                o[4 * d4 + 1] += pj * vv.y;
                o[4 * d4 + 2] += pj * vv.z;
                o[4 * d4 + 3] += pj * vv.w;
            }
        }
        __syncthreads();
    }

    const float inv = 1.f / lrow;
    float* orow = g_att + (b * TDIM + r) * DDIM + h * HDIM;
#pragma unroll
    for (int d4 = 0; d4 < 16; d4++) {
        *(float4*)(orow + 4 * d4) = make_float4(o[4 * d4] * inv, o[4 * d4 + 1] * inv,
                                                o[4 * d4 + 2] * inv, o[4 * d4 + 3] * inv);
    }
}

// ---------------------------------------------------------------------------
// Inputs (metadata order): x, Wk, Wq, Wv, Wo. Output fp32 [8,1024,1024].
// ---------------------------------------------------------------------------
extern "C" void kernel_launch(void* const* d_in, const int* in_sizes, int n_in,
                              void* d_out, int out_size)
{
    const float* x  = (const float*)d_in[0];
    const float* Wk = (const float*)d_in[1];
    const float* Wq = (const float*)d_in[2];
    const float* Wv = (const float*)d_in[3];
    const float* Wo = (const float*)d_in[4];
    float* out = (float*)d_out;

    dim3 gqkv(8, 64, 3);
    qkv_kernel<<<gqkv, 256>>>(x, Wk, Wq, Wv);

    dim3 gattn(NBATCH * NHEADS, TDIM / 128);
    attn_kernel<<<gattn, 128>>>();

    dim3 gout(8, 64);
    out_kernel<<<gout, 256>>>(Wo, out);
}

// round 3
// speedup vs baseline: 1.3890x; 1.3890x over previous
#include <cuda_runtime.h>
#include <cuda_bf16.h>
#include <math_constants.h>
#include <cstdint>

#define TDIM   1024
#define DDIM   1024
#define NBATCH 8
#define NHEADS 16
#define HDIM   64
#define MROWS  (NBATCH * TDIM)   // 8192

// ---------------- scratch (__device__ globals: allocation-free rule) --------
__device__ __align__(256) float g_q[MROWS * DDIM];
__device__ __align__(256) float g_k[MROWS * DDIM];
__device__ __align__(256) float g_v[MROWS * DDIM];
__device__ __align__(256) __nv_bfloat16 g_xhi[MROWS * DDIM];
__device__ __align__(256) __nv_bfloat16 g_xlo[MROWS * DDIM];
__device__ __align__(256) __nv_bfloat16 g_atthi[MROWS * DDIM];
__device__ __align__(256) __nv_bfloat16 g_attlo[MROWS * DDIM];
__device__ __align__(256) __nv_bfloat16 g_wqhi[DDIM * DDIM];
__device__ __align__(256) __nv_bfloat16 g_wqlo[DDIM * DDIM];
__device__ __align__(256) __nv_bfloat16 g_wkhi[DDIM * DDIM];
__device__ __align__(256) __nv_bfloat16 g_wklo[DDIM * DDIM];
__device__ __align__(256) __nv_bfloat16 g_wvhi[DDIM * DDIM];
__device__ __align__(256) __nv_bfloat16 g_wvlo[DDIM * DDIM];
__device__ __align__(256) __nv_bfloat16 g_wohi[DDIM * DDIM];
__device__ __align__(256) __nv_bfloat16 g_wolo[DDIM * DDIM];

// ---------------- PTX helpers ----------------------------------------------
__device__ __forceinline__ uint32_t smem_u32(const void* p) {
    uint32_t a;
    asm("{ .reg .u64 t; cvta.to.shared.u64 t, %1; cvt.u32.u64 %0, t; }" : "=r"(a) : "l"(p));
    return a;
}
__device__ __forceinline__ void cp16(uint32_t dst, const void* src) {
    asm volatile("cp.async.cg.shared.global [%0], [%1], 16;" :: "r"(dst), "l"(src));
}
#define CP_COMMIT()  asm volatile("cp.async.commit_group;" ::: "memory")
#define CP_WAIT(n)   asm volatile("cp.async.wait_group %0;" :: "n"(n) : "memory")

#define LDSM_X4(r0, r1, r2, r3, a)                                                 \
    asm volatile("ldmatrix.sync.aligned.m8n8.x4.shared.b16 {%0,%1,%2,%3}, [%4];"   \
                 : "=r"(r0), "=r"(r1), "=r"(r2), "=r"(r3) : "r"(a))

__device__ __forceinline__ void mma16816(float* c, const uint32_t* a, const uint32_t* b)
{
    asm volatile(
        "mma.sync.aligned.m16n8k16.row.col.f32.bf16.bf16.f32 "
        "{%0,%1,%2,%3}, {%4,%5,%6,%7}, {%8,%9}, {%0,%1,%2,%3};"
        : "+f"(c[0]), "+f"(c[1]), "+f"(c[2]), "+f"(c[3])
        : "r"(a[0]), "r"(a[1]), "r"(a[2]), "r"(a[3]), "r"(b[0]), "r"(b[1]));
}

// ---------------------------------------------------------------------------
// bf16 3-term split GEMM via mma.sync:  C[128m,128n] = A·B^T, fp32 accum.
// A: [8192,1024] (hi/lo), B: [1024,1024] (hi/lo), row-major K-contiguous bf16.
// CTA 128x128, 8 warps (2x4), warp 64x32, K-chunk 32, 3-stage cp.async.
// Smem operand layout: 128 rows x 32 bf16, row stride 80B. r*80 mod 128 =
// 16*(5r mod 8) permutes the 8 16B-slots -> ldmatrix phases conflict-free.
// ---------------------------------------------------------------------------
#define STRIDE 80
#define OPB    10240               // 128 * 80
#define STGB   (4 * OPB)           // Ahi, Alo, Bhi, Blo
#define NSTG   3
#define SMEM_DYN (NSTG * STGB)     // 122880

__device__ __forceinline__ void bfmma_gemm(const __nv_bfloat16* __restrict__ Ahi,
                                           const __nv_bfloat16* __restrict__ Alo,
                                           const __nv_bfloat16* __restrict__ Bhi,
                                           const __nv_bfloat16* __restrict__ Blo,
                                           float* __restrict__ C)
{
    extern __shared__ char smraw[];
    const uint32_t s0 = smem_u32(smraw);

    const int tid  = threadIdx.x;
    const int warp = tid >> 5;
    const int lane = tid & 31;
    const int m0   = blockIdx.y * 128;
    const int n0   = blockIdx.x * 128;
    const int wm   = (warp >> 2) * 64;   // warp row offset in tile
    const int wn   = (warp & 3) * 32;    // warp col offset in tile

    // loader role: 64 threads per operand
    const int op  = tid >> 6;
    const int t64 = tid & 63;
    const char* gbase;
    if (op == 0)      gbase = (const char*)(Ahi + (size_t)m0 * DDIM);
    else if (op == 1) gbase = (const char*)(Alo + (size_t)m0 * DDIM);
    else if (op == 2) gbase = (const char*)(Bhi + (size_t)n0 * DDIM);
    else              gbase = (const char*)(Blo + (size_t)n0 * DDIM);

#define LOAD_STAGE(kc, st)                                                     \
    {                                                                          \
        const uint32_t sb = s0 + (st) * STGB + op * OPB;                       \
        _Pragma("unroll")                                                      \
        for (int j = 0; j < 8; j++) {                                          \
            int id = t64 + (j << 6);                                           \
            int row = id >> 2, c = id & 3;                                     \
            cp16(sb + row * STRIDE + c * 16,                                   \
                 gbase + (size_t)row * 2048 + (kc) * 64 + c * 16);             \
        }                                                                      \
    }

    float acc[4][4][4];
#pragma unroll
    for (int i = 0; i < 4; i++)
#pragma unroll
        for (int j = 0; j < 4; j++)
#pragma unroll
            for (int r = 0; r < 4; r++) acc[i][j][r] = 0.f;

    LOAD_STAGE(0, 0); CP_COMMIT();
    LOAD_STAGE(1, 1); CP_COMMIT();

    const int arow_b = (lane & 15);     // row within 16-row tile for ldsm
    const int ahalf  = (lane >> 4);     // which 16B chunk half

    for (int i = 0; i < 32; i++) {
        if (i < 30) { CP_WAIT(1); } else if (i == 30) { CP_WAIT(0); }
        __syncthreads();
        if (i < 30) { LOAD_STAGE(i + 2, (i + 2) % NSTG); CP_COMMIT(); }

        const uint32_t base = s0 + (i % NSTG) * STGB;
#pragma unroll
        for (int g = 0; g < 2; g++) {
            const uint32_t coff = (uint32_t)(2 * g + ahalf) * 16;
            uint32_t ah[4][4], al[4][4], bh[4][2], bl[4][2];
#pragma unroll
            for (int mi = 0; mi < 4; mi++) {
                const uint32_t ra = (uint32_t)(wm + mi * 16 + arow_b) * STRIDE + coff;
                LDSM_X4(ah[mi][0], ah[mi][1], ah[mi][2], ah[mi][3], base + ra);
                LDSM_X4(al[mi][0], al[mi][1], al[mi][2], al[mi][3], base + OPB + ra);
            }
#pragma unroll
            for (int jp = 0; jp < 2; jp++) {
                const uint32_t rb = (uint32_t)(wn + jp * 16 + arow_b) * STRIDE + coff;
                uint32_t t0, t1, t2, t3;
                LDSM_X4(t0, t1, t2, t3, base + 2 * OPB + rb);
                bh[2 * jp][0] = t0; bh[2 * jp][1] = t2;
                bh[2 * jp + 1][0] = t1; bh[2 * jp + 1][1] = t3;
                LDSM_X4(t0, t1, t2, t3, base + 3 * OPB + rb);
                bl[2 * jp][0] = t0; bl[2 * jp][1] = t2;
                bl[2 * jp + 1][0] = t1; bl[2 * jp + 1][1] = t3;
            }
#pragma unroll
            for (int mi = 0; mi < 4; mi++)
#pragma unroll
                for (int nj = 0; nj < 4; nj++) {
                    mma16816(acc[mi][nj], ah[mi], bh[nj]);
                    mma16816(acc[mi][nj], ah[mi], bl[nj]);
                    mma16816(acc[mi][nj], al[mi], bh[nj]);
                }
        }
    }

    // epilogue: c-frag (m16n8): c0,c1 -> (row t/4, col 2(t&3)); c2,c3 -> row+8
    const int crow = lane >> 2;
    const int ccol = (lane & 3) * 2;
#pragma unroll
    for (int mi = 0; mi < 4; mi++)
#pragma unroll
        for (int nj = 0; nj < 4; nj++) {
            float* p = C + (size_t)(m0 + wm + mi * 16 + crow) * DDIM + (n0 + wn + nj * 8 + ccol);
            *(float2*)p = make_float2(acc[mi][nj][0], acc[mi][nj][1]);
            *(float2*)(p + 8 * DDIM) = make_float2(acc[mi][nj][2], acc[mi][nj][3]);
        }
#undef LOAD_STAGE
}

__global__ void __launch_bounds__(256, 1) qkv_tc_kernel()
{
    if (blockIdx.z == 0)      bfmma_gemm(g_xhi, g_xlo, g_wqhi, g_wqlo, g_q);
    else if (blockIdx.z == 1) bfmma_gemm(g_xhi, g_xlo, g_wkhi, g_wklo, g_k);
    else                      bfmma_gemm(g_xhi, g_xlo, g_wvhi, g_wvlo, g_v);
}

__global__ void __launch_bounds__(256, 1) out_tc_kernel(float* __restrict__ out)
{
    bfmma_gemm(g_atthi, g_attlo, g_wohi, g_wolo, out);
}

// ---------------------------------------------------------------------------
// fp32 -> bf16 hi/lo split conversion
// ---------------------------------------------------------------------------
__device__ __forceinline__ void split4(float4 v, __nv_bfloat162* hi, __nv_bfloat162* lo, int i2)
{
    __nv_bfloat16 hx = __float2bfloat16(v.x), hy = __float2bfloat16(v.y);
    __nv_bfloat16 hz = __float2bfloat16(v.z), hw = __float2bfloat16(v.w);
    __nv_bfloat16 lx = __float2bfloat16(v.x - __bfloat162float(hx));
    __nv_bfloat16 ly = __float2bfloat16(v.y - __bfloat162float(hy));
    __nv_bfloat16 lz = __float2bfloat16(v.z - __bfloat162float(hz));
    __nv_bfloat16 lw = __float2bfloat16(v.w - __bfloat162float(hw));
    hi[i2]     = __nv_bfloat162(hx, hy);
    hi[i2 + 1] = __nv_bfloat162(hz, hw);
    lo[i2]     = __nv_bfloat162(lx, ly);
    lo[i2 + 1] = __nv_bfloat162(lz, lw);
}

__global__ void __launch_bounds__(256) cvt_x_kernel(const float4* __restrict__ src)
{
    int i = blockIdx.x * 256 + threadIdx.x;
    split4(src[i], (__nv_bfloat162*)g_xhi, (__nv_bfloat162*)g_xlo, 2 * i);
}

__global__ void __launch_bounds__(256) cvt_w_kernel(const float4* __restrict__ wk,
                                                    const float4* __restrict__ wq,
                                                    const float4* __restrict__ wv,
                                                    const float4* __restrict__ wo)
{
    int i = blockIdx.x * 256 + threadIdx.x;
    const float4* src;
    __nv_bfloat162 *hi, *lo;
    switch (blockIdx.z) {
        case 0:  src = wq; hi = (__nv_bfloat162*)g_wqhi; lo = (__nv_bfloat162*)g_wqlo; break;
        case 1:  src = wk; hi = (__nv_bfloat162*)g_wkhi; lo = (__nv_bfloat162*)g_wklo; break;
        case 2:  src = wv; hi = (__nv_bfloat162*)g_wvhi; lo = (__nv_bfloat162*)g_wvlo; break;
        default: src = wo; hi = (__nv_bfloat162*)g_wohi; lo = (__nv_bfloat162*)g_wolo; break;
    }
    split4(src[i], hi, lo, 2 * i);
}

// ---------------------------------------------------------------------------
// Causal flash attention, fp32 (unchanged); epilogue emits bf16 hi/lo.
// ---------------------------------------------------------------------------
__global__ void __launch_bounds__(128) attn_kernel()
{
    __shared__ float kt[16][64];
    __shared__ float vt[16][64];

    const int tid = threadIdx.x;
    const int bh  = blockIdx.x;
    const int b   = bh >> 4;
    const int h   = bh & 15;
    const int r   = blockIdx.y * 128 + tid;

    const float* qrow = g_q + (size_t)(b * TDIM + r) * DDIM + h * HDIM;
    float q[64];
#pragma unroll
    for (int i = 0; i < 16; i++) {
        float4 t = *(const float4*)(qrow + 4 * i);
        q[4 * i] = t.x; q[4 * i + 1] = t.y; q[4 * i + 2] = t.z; q[4 * i + 3] = t.w;
    }

    float o[64];
#pragma unroll
    for (int d = 0; d < 64; d++) o[d] = 0.f;
    float mrow = -CUDART_INF_F;
    float lrow = 0.f;

    const float* kbase = g_k + (size_t)b * TDIM * DDIM + h * HDIM;
    const float* vbase = g_v + (size_t)b * TDIM * DDIM + h * HDIM;
    const int nkb = blockIdx.y * 8 + 8;

    for (int kb = 0; kb < nkb; kb++) {
#pragma unroll
        for (int it = 0; it < 2; it++) {
            int i   = tid * 2 + it;
            int row = i >> 4;
            int c4  = (i & 15) * 4;
            *(float4*)&kt[row][c4] = *(const float4*)(kbase + (size_t)(kb * 16 + row) * DDIM + c4);
            *(float4*)&vt[row][c4] = *(const float4*)(vbase + (size_t)(kb * 16 + row) * DDIM + c4);
        }
        __syncthreads();

        const int col0 = kb * 16;
        float s[16];
#pragma unroll
        for (int j = 0; j < 16; j++) {
            float a0 = 0.f, a1 = 0.f, a2 = 0.f, a3 = 0.f;
#pragma unroll
            for (int d4 = 0; d4 < 16; d4++) {
                float4 kv = *(const float4*)&kt[j][4 * d4];
                a0 += q[4 * d4]     * kv.x;
                a1 += q[4 * d4 + 1] * kv.y;
                a2 += q[4 * d4 + 2] * kv.z;
                a3 += q[4 * d4 + 3] * kv.w;
            }
            float sv = (a0 + a1) + (a2 + a3);
            s[j] = (col0 + j <= r) ? sv * 0.125f : -CUDART_INF_F;
        }

        float mnew = mrow;
#pragma unroll
        for (int j = 0; j < 16; j++) mnew = fmaxf(mnew, s[j]);

        float scale = __expf(mrow - mnew);
        float p[16];
        float psum = 0.f;
#pragma unroll
        for (int j = 0; j < 16; j++) { p[j] = __expf(s[j] - mnew); psum += p[j]; }

        mrow = mnew;
        lrow = lrow * scale + psum;
#pragma unroll
        for (int d = 0; d < 64; d++) o[d] *= scale;
#pragma unroll
        for (int j = 0; j < 16; j++) {
            float pj = p[j];
#pragma unroll
            for (int d4 = 0; d4 < 16; d4++) {
                float4 vv = *(const float4*)&vt[j][4 * d4];
                o[4 * d4]     += pj * vv.x;
                o[4 * d4 + 1] += pj * vv.y;
                o[4 * d4 + 2] += pj * vv.z;
                o[4 * d4 + 3] += pj * vv.w;
            }
        }
        __syncthreads();
    }

    const float inv = 1.f / lrow;
    const size_t base = (size_t)(b * TDIM + r) * DDIM + h * HDIM;
    __nv_bfloat162* hih = (__nv_bfloat162*)(g_atthi + base);
    __nv_bfloat162* loh = (__nv_bfloat162*)(g_attlo + base);
#pragma unroll
    for (int d2 = 0; d2 < 32; d2++) {
        float v0 = o[2 * d2] * inv, v1 = o[2 * d2 + 1] * inv;
        __nv_bfloat16 h0 = __float2bfloat16(v0), h1 = __float2bfloat16(v1);
        __nv_bfloat16 l0 = __float2bfloat16(v0 - __bfloat162float(h0));
        __nv_bfloat16 l1 = __float2bfloat16(v1 - __bfloat162float(h1));
        hih[d2] = __nv_bfloat162(h0, h1);
        loh[d2] = __nv_bfloat162(l0, l1);
    }
}

// ---------------------------------------------------------------------------
// Inputs (metadata order): x, Wk, Wq, Wv, Wo. Output fp32 [8,1024,1024].
// ---------------------------------------------------------------------------
extern "C" void kernel_launch(void* const* d_in, const int* in_sizes, int n_in,
                              void* d_out, int out_size)
{
    const float* x  = (const float*)d_in[0];
    const float* Wk = (const float*)d_in[1];
    const float* Wq = (const float*)d_in[2];
    const float* Wv = (const float*)d_in[3];
    const float* Wo = (const float*)d_in[4];
    float* out = (float*)d_out;

    static int configured = 0;
    if (!configured) {
        cudaFuncSetAttribute(qkv_tc_kernel, cudaFuncAttributeMaxDynamicSharedMemorySize, SMEM_DYN);
        cudaFuncSetAttribute(out_tc_kernel, cudaFuncAttributeMaxDynamicSharedMemorySize, SMEM_DYN);
        configured = 1;
    }

    cvt_x_kernel<<<8192, 256>>>((const float4*)x);
    cvt_w_kernel<<<dim3(1024, 1, 4), 256>>>((const float4*)Wk, (const float4*)Wq,
                                            (const float4*)Wv, (const float4*)Wo);

    qkv_tc_kernel<<<dim3(8, 64, 3), 256, SMEM_DYN>>>();

    attn_kernel<<<dim3(NBATCH * NHEADS, TDIM / 128), 128>>>();

    out_tc_kernel<<<dim3(8, 64), 256, SMEM_DYN>>>(out);
}

// round 4
// speedup vs baseline: 2.3721x; 1.7077x over previous
#include <cuda_runtime.h>
#include <cuda_bf16.h>
#include <math_constants.h>
#include <cstdint>

#define TDIM   1024
#define DDIM   1024
#define NBATCH 8
#define NHEADS 16
#define MROWS  (NBATCH * TDIM)   // 8192

// ---------------- scratch (__device__ globals) ------------------------------
__device__ __align__(256) __nv_bfloat16 g_xhi[MROWS * DDIM];
__device__ __align__(256) __nv_bfloat16 g_xlo[MROWS * DDIM];
__device__ __align__(256) __nv_bfloat16 g_qhi[MROWS * DDIM];
__device__ __align__(256) __nv_bfloat16 g_qlo[MROWS * DDIM];
__device__ __align__(256) __nv_bfloat16 g_khi[MROWS * DDIM];
__device__ __align__(256) __nv_bfloat16 g_klo[MROWS * DDIM];
__device__ __align__(256) __nv_bfloat16 g_vhi[MROWS * DDIM];
__device__ __align__(256) __nv_bfloat16 g_vlo[MROWS * DDIM];
__device__ __align__(256) __nv_bfloat16 g_atthi[MROWS * DDIM];
__device__ __align__(256) __nv_bfloat16 g_attlo[MROWS * DDIM];
__device__ __align__(256) __nv_bfloat16 g_wqhi[DDIM * DDIM];
__device__ __align__(256) __nv_bfloat16 g_wqlo[DDIM * DDIM];
__device__ __align__(256) __nv_bfloat16 g_wkhi[DDIM * DDIM];
__device__ __align__(256) __nv_bfloat16 g_wklo[DDIM * DDIM];
__device__ __align__(256) __nv_bfloat16 g_wvhi[DDIM * DDIM];
__device__ __align__(256) __nv_bfloat16 g_wvlo[DDIM * DDIM];
__device__ __align__(256) __nv_bfloat16 g_wohi[DDIM * DDIM];
__device__ __align__(256) __nv_bfloat16 g_wolo[DDIM * DDIM];

// ---------------- PTX helpers ----------------------------------------------
__device__ __forceinline__ uint32_t smem_u32(const void* p) {
    uint32_t a;
    asm("{ .reg .u64 t; cvta.to.shared.u64 t, %1; cvt.u32.u64 %0, t; }" : "=r"(a) : "l"(p));
    return a;
}
__device__ __forceinline__ void cp16(uint32_t dst, const void* src) {
    asm volatile("cp.async.cg.shared.global [%0], [%1], 16;" :: "r"(dst), "l"(src));
}
#define CP_COMMIT()  asm volatile("cp.async.commit_group;" ::: "memory")
#define CP_WAIT(n)   asm volatile("cp.async.wait_group %0;" :: "n"(n) : "memory")

#define LDSM_X4(r0, r1, r2, r3, a)                                                 \
    asm volatile("ldmatrix.sync.aligned.m8n8.x4.shared.b16 {%0,%1,%2,%3}, [%4];"   \
                 : "=r"(r0), "=r"(r1), "=r"(r2), "=r"(r3) : "r"(a))
#define LDSM_X4_T(r0, r1, r2, r3, a)                                               \
    asm volatile("ldmatrix.sync.aligned.m8n8.x4.trans.shared.b16 {%0,%1,%2,%3}, [%4];" \
                 : "=r"(r0), "=r"(r1), "=r"(r2), "=r"(r3) : "r"(a))

__device__ __forceinline__ void mma16816(float* c, const uint32_t* a, const uint32_t* b)
{
    asm volatile(
        "mma.sync.aligned.m16n8k16.row.col.f32.bf16.bf16.f32 "
        "{%0,%1,%2,%3}, {%4,%5,%6,%7}, {%8,%9}, {%0,%1,%2,%3};"
        : "+f"(c[0]), "+f"(c[1]), "+f"(c[2]), "+f"(c[3])
        : "r"(a[0]), "r"(a[1]), "r"(a[2]), "r"(a[3]), "r"(b[0]), "r"(b[1]));
}

__device__ __forceinline__ void splitpack(float a, float b, uint32_t& hi, uint32_t& lo)
{
    __nv_bfloat16 ha = __float2bfloat16(a), hb = __float2bfloat16(b);
    __nv_bfloat16 la = __float2bfloat16(a - __bfloat162float(ha));
    __nv_bfloat16 lb = __float2bfloat16(b - __bfloat162float(hb));
    __nv_bfloat162 H(ha, hb), L(la, lb);
    hi = *(uint32_t*)&H;
    lo = *(uint32_t*)&L;
}

// ---------------------------------------------------------------------------
// bf16 3-term split GEMM via mma.sync (as round 3), templated epilogue:
// MODE 0: fp32 C.   MODE 1: scale then split to bf16 hi/lo outputs.
// ---------------------------------------------------------------------------
#define STRIDE 80
#define OPB    10240
#define STGB   (4 * OPB)
#define NSTG   3
#define SMEM_DYN (NSTG * STGB)

template<int MODE>
__device__ __forceinline__ void bfmma_gemm(const __nv_bfloat16* __restrict__ Ahi,
                                           const __nv_bfloat16* __restrict__ Alo,
                                           const __nv_bfloat16* __restrict__ Bhi,
                                           const __nv_bfloat16* __restrict__ Blo,
                                           float* __restrict__ C,
                                           __nv_bfloat16* __restrict__ Chi,
                                           __nv_bfloat16* __restrict__ Clo,
                                           float scale)
{
    extern __shared__ char smraw[];
    const uint32_t s0 = smem_u32(smraw);

    const int tid  = threadIdx.x;
    const int warp = tid >> 5;
    const int lane = tid & 31;
    const int m0   = blockIdx.y * 128;
    const int n0   = blockIdx.x * 128;
    const int wm   = (warp >> 2) * 64;
    const int wn   = (warp & 3) * 32;

    const int op  = tid >> 6;
    const int t64 = tid & 63;
    const char* gbase;
    if (op == 0)      gbase = (const char*)(Ahi + (size_t)m0 * DDIM);
    else if (op == 1) gbase = (const char*)(Alo + (size_t)m0 * DDIM);
    else if (op == 2) gbase = (const char*)(Bhi + (size_t)n0 * DDIM);
    else              gbase = (const char*)(Blo + (size_t)n0 * DDIM);

#define LOAD_STAGE(kc, st)                                                     \
    {                                                                          \
        const uint32_t sb = s0 + (st) * STGB + op * OPB;                       \
        _Pragma("unroll")                                                      \
        for (int j = 0; j < 8; j++) {                                          \
            int id = t64 + (j << 6);                                           \
            int row = id >> 2, c = id & 3;                                     \
            cp16(sb + row * STRIDE + c * 16,                                   \
                 gbase + (size_t)row * 2048 + (kc) * 64 + c * 16);             \
        }                                                                      \
    }

    float acc[4][4][4];
#pragma unroll
    for (int i = 0; i < 4; i++)
#pragma unroll
        for (int j = 0; j < 4; j++)
#pragma unroll
            for (int r = 0; r < 4; r++) acc[i][j][r] = 0.f;

    LOAD_STAGE(0, 0); CP_COMMIT();
    LOAD_STAGE(1, 1); CP_COMMIT();

    const int arow_b = (lane & 15);
    const int ahalf  = (lane >> 4);

    for (int i = 0; i < 32; i++) {
        if (i < 30) { CP_WAIT(1); } else if (i == 30) { CP_WAIT(0); }
        __syncthreads();
        if (i < 30) { LOAD_STAGE(i + 2, (i + 2) % NSTG); CP_COMMIT(); }

        const uint32_t base = s0 + (i % NSTG) * STGB;
#pragma unroll
        for (int g = 0; g < 2; g++) {
            const uint32_t coff = (uint32_t)(2 * g + ahalf) * 16;
            uint32_t ah[4][4], al[4][4], bh[4][2], bl[4][2];
#pragma unroll
            for (int mi = 0; mi < 4; mi++) {
                const uint32_t ra = (uint32_t)(wm + mi * 16 + arow_b) * STRIDE + coff;
                LDSM_X4(ah[mi][0], ah[mi][1], ah[mi][2], ah[mi][3], base + ra);
                LDSM_X4(al[mi][0], al[mi][1], al[mi][2], al[mi][3], base + OPB + ra);
            }
#pragma unroll
            for (int jp = 0; jp < 2; jp++) {
                const uint32_t rbo = (uint32_t)(wn + jp * 16 + arow_b) * STRIDE + coff;
                uint32_t t0, t1, t2, t3;
                LDSM_X4(t0, t1, t2, t3, base + 2 * OPB + rbo);
                bh[2 * jp][0] = t0; bh[2 * jp][1] = t2;
                bh[2 * jp + 1][0] = t1; bh[2 * jp + 1][1] = t3;
                LDSM_X4(t0, t1, t2, t3, base + 3 * OPB + rbo);
                bl[2 * jp][0] = t0; bl[2 * jp][1] = t2;
                bl[2 * jp + 1][0] = t1; bl[2 * jp + 1][1] = t3;
            }
#pragma unroll
            for (int mi = 0; mi < 4; mi++)
#pragma unroll
                for (int nj = 0; nj < 4; nj++) {
                    mma16816(acc[mi][nj], ah[mi], bh[nj]);
                    mma16816(acc[mi][nj], ah[mi], bl[nj]);
                    mma16816(acc[mi][nj], al[mi], bh[nj]);
                }
        }
    }

    const int crow = lane >> 2;
    const int ccol = (lane & 3) * 2;
#pragma unroll
    for (int mi = 0; mi < 4; mi++)
#pragma unroll
        for (int nj = 0; nj < 4; nj++) {
            const size_t r0 = (size_t)(m0 + wm + mi * 16 + crow) * DDIM + (n0 + wn + nj * 8 + ccol);
            if (MODE == 0) {
                *(float2*)(C + r0) = make_float2(acc[mi][nj][0], acc[mi][nj][1]);
                *(float2*)(C + r0 + 8 * DDIM) = make_float2(acc[mi][nj][2], acc[mi][nj][3]);
            } else {
                uint32_t hi, lo;
                splitpack(acc[mi][nj][0] * scale, acc[mi][nj][1] * scale, hi, lo);
                *(uint32_t*)(Chi + r0) = hi;
                *(uint32_t*)(Clo + r0) = lo;
                splitpack(acc[mi][nj][2] * scale, acc[mi][nj][3] * scale, hi, lo);
                *(uint32_t*)(Chi + r0 + 8 * DDIM) = hi;
                *(uint32_t*)(Clo + r0 + 8 * DDIM) = lo;
            }
        }
#undef LOAD_STAGE
}

__global__ void __launch_bounds__(256, 1) qkv_tc_kernel()
{
    if (blockIdx.z == 0)                       // Q pre-scaled by 1/sqrt(64)
        bfmma_gemm<1>(g_xhi, g_xlo, g_wqhi, g_wqlo, nullptr, g_qhi, g_qlo, 0.125f);
    else if (blockIdx.z == 1)
        bfmma_gemm<1>(g_xhi, g_xlo, g_wkhi, g_wklo, nullptr, g_khi, g_klo, 1.0f);
    else
        bfmma_gemm<1>(g_xhi, g_xlo, g_wvhi, g_wvlo, nullptr, g_vhi, g_vlo, 1.0f);
}

__global__ void __launch_bounds__(256, 1) out_tc_kernel(float* __restrict__ out)
{
    bfmma_gemm<0>(g_atthi, g_attlo, g_wohi, g_wolo, out, nullptr, nullptr, 1.0f);
}

// ---------------------------------------------------------------------------
// fp32 -> bf16 hi/lo split conversions
// ---------------------------------------------------------------------------
__device__ __forceinline__ void split4(float4 v, __nv_bfloat162* hi, __nv_bfloat162* lo, int i2)
{
    uint32_t h0, l0, h1, l1;
    splitpack(v.x, v.y, h0, l0);
    splitpack(v.z, v.w, h1, l1);
    ((uint32_t*)hi)[i2] = h0; ((uint32_t*)hi)[i2 + 1] = h1;
    ((uint32_t*)lo)[i2] = l0; ((uint32_t*)lo)[i2 + 1] = l1;
}

__global__ void __launch_bounds__(256) cvt_x_kernel(const float4* __restrict__ src)
{
    int i = blockIdx.x * 256 + threadIdx.x;
    split4(src[i], (__nv_bfloat162*)g_xhi, (__nv_bfloat162*)g_xlo, 2 * i);
}

__global__ void __launch_bounds__(256) cvt_w_kernel(const float4* __restrict__ wk,
                                                    const float4* __restrict__ wq,
                                                    const float4* __restrict__ wv,
                                                    const float4* __restrict__ wo)
{
    int i = blockIdx.x * 256 + threadIdx.x;
    const float4* src;
    __nv_bfloat162 *hi, *lo;
    switch (blockIdx.z) {
        case 0:  src = wq; hi = (__nv_bfloat162*)g_wqhi; lo = (__nv_bfloat162*)g_wqlo; break;
        case 1:  src = wk; hi = (__nv_bfloat162*)g_wkhi; lo = (__nv_bfloat162*)g_wklo; break;
        case 2:  src = wv; hi = (__nv_bfloat162*)g_wvhi; lo = (__nv_bfloat162*)g_wvlo; break;
        default: src = wo; hi = (__nv_bfloat162*)g_wohi; lo = (__nv_bfloat162*)g_wolo; break;
    }
    split4(src[i], hi, lo, 2 * i);
}

// ---------------------------------------------------------------------------
// Tensor-core causal flash attention, bf16 3-term split, fp32 accum.
// CTA = 128 q-rows x one (b,h); 4 warps, 32 rows/warp. KV tiles of 64 keys,
// double-buffered cp.async. Scores arrive pre-scaled (Q *= 0.125 in proj).
// Smem tiles: 64 rows x 64 bf16, row stride 144B (4r mod 32 bank rotation ->
// conflict-free ldmatrix).
// ---------------------------------------------------------------------------
#define AT_ROWB  144
#define AT_OP    9216              // 64 * 144
#define AT_STG   (4 * AT_OP)       // khi, klo, vhi, vlo
#define AT_SMEM  (2 * AT_STG)      // 73728

__global__ void __launch_bounds__(128, 2) attn_tc_kernel()
{
    extern __shared__ char smraw[];
    const uint32_t s0 = smem_u32(smraw);
    const int tid  = threadIdx.x;
    const int warp = tid >> 5;
    const int lane = tid & 31;
    const int y    = 7 - (int)blockIdx.x;      // heavy blocks first
    const int bh   = blockIdx.y;
    const int b    = bh >> 4, h = bh & 15;
    const int qb   = y * 128;
    const int nt   = 2 * y + 2;                // KV tiles of 64
    const size_t rb = (size_t)b * TDIM;

    // ---- stage Q (hi/lo) 128x64 -> smem, then ldmatrix to regs -------------
    {
        const int op = tid >> 6, t64 = tid & 63;
        const __nv_bfloat16* src = (op ? g_qlo : g_qhi) + (rb + qb) * DDIM + h * 64;
        const uint32_t dst = s0 + op * 18432;
#pragma unroll
        for (int j = 0; j < 16; j++) {
            int id = t64 + (j << 6);
            int row = id >> 3, c = id & 7;
            cp16(dst + row * AT_ROWB + c * 16, src + (size_t)row * DDIM + c * 8);
        }
        CP_COMMIT(); CP_WAIT(0);
        __syncthreads();
    }

    uint32_t qh[2][4][4], ql[2][4][4];
    {
        const int l15 = lane & 15, lh = lane >> 4;
#pragma unroll
        for (int mi = 0; mi < 2; mi++)
#pragma unroll
            for (int ks = 0; ks < 4; ks++) {
                uint32_t ad = s0 + (uint32_t)(warp * 32 + mi * 16 + l15) * AT_ROWB
                              + (uint32_t)(ks * 16 + lh * 8) * 2;
                LDSM_X4(qh[mi][ks][0], qh[mi][ks][1], qh[mi][ks][2], qh[mi][ks][3], ad);
                LDSM_X4(ql[mi][ks][0], ql[mi][ks][1], ql[mi][ks][2], ql[mi][ks][3], ad + 18432);
            }
    }
    __syncthreads();   // Q smem region free before KV loads reuse it

    float O[2][8][4], m[2][2], l[2][2];
#pragma unroll
    for (int mi = 0; mi < 2; mi++) {
        m[mi][0] = m[mi][1] = -1e30f;
        l[mi][0] = l[mi][1] = 0.f;
#pragma unroll
        for (int nj = 0; nj < 8; nj++)
#pragma unroll
            for (int c = 0; c < 4; c++) O[mi][nj][c] = 0.f;
    }

    const int crow = lane >> 2, ccol = (lane & 3) * 2;

#define KV_LOAD(t, st)                                                              \
    {                                                                               \
        const int op = tid >> 5;                                                    \
        const __nv_bfloat16* sc =                                                   \
            (op == 0 ? g_khi : op == 1 ? g_klo : op == 2 ? g_vhi : g_vlo)           \
            + (rb + (t) * 64) * DDIM + h * 64;                                      \
        const uint32_t ds = s0 + (st) * AT_STG + op * AT_OP;                        \
        _Pragma("unroll")                                                           \
        for (int j = 0; j < 16; j++) {                                              \
            int id = lane + (j << 5);                                               \
            int row = id >> 3, c = id & 7;                                          \
            cp16(ds + row * AT_ROWB + c * 16, sc + (size_t)row * DDIM + c * 8);     \
        }                                                                           \
    }

    KV_LOAD(0, 0); CP_COMMIT();
    if (nt > 1) KV_LOAD(1, 1);
    CP_COMMIT();

    const int l15 = lane & 15, lh = lane >> 4;
    const int koffV = (lane & 7) + (((lane >> 3) & 1) << 3);
    const int doffV = (lane >> 4) << 3;

    for (int t = 0; t < nt; t++) {
        CP_WAIT(1);
        __syncthreads();
        const uint32_t kb = s0 + (t & 1) * AT_STG;

        // ---- S = Q K^T (3-term) -------------------------------------------
        float S[2][8][4];
#pragma unroll
        for (int mi = 0; mi < 2; mi++)
#pragma unroll
            for (int nj = 0; nj < 8; nj++)
#pragma unroll
                for (int c = 0; c < 4; c++) S[mi][nj][c] = 0.f;

#pragma unroll
        for (int ks = 0; ks < 4; ks++) {
#pragma unroll
            for (int nj2 = 0; nj2 < 4; nj2++) {
                const uint32_t ad = kb + (uint32_t)(nj2 * 16 + l15) * AT_ROWB
                                    + (uint32_t)(ks * 16 + lh * 8) * 2;
                uint32_t kh0, kh1, kh2, kh3, kl0, kl1, kl2, kl3;
                LDSM_X4(kh0, kh1, kh2, kh3, ad);
                LDSM_X4(kl0, kl1, kl2, kl3, ad + AT_OP);
                uint32_t b0h[2] = {kh0, kh2}, b1h[2] = {kh1, kh3};
                uint32_t b0l[2] = {kl0, kl2}, b1l[2] = {kl1, kl3};
#pragma unroll
                for (int mi = 0; mi < 2; mi++) {
                    mma16816(S[mi][2 * nj2], qh[mi][ks], b0h);
                    mma16816(S[mi][2 * nj2], qh[mi][ks], b0l);
                    mma16816(S[mi][2 * nj2], ql[mi][ks], b0h);
                    mma16816(S[mi][2 * nj2 + 1], qh[mi][ks], b1h);
                    mma16816(S[mi][2 * nj2 + 1], qh[mi][ks], b1l);
                    mma16816(S[mi][2 * nj2 + 1], ql[mi][ks], b1h);
                }
            }
        }

        // ---- online softmax -----------------------------------------------
        const bool masked = (t >= nt - 2);
#pragma unroll
        for (int mi = 0; mi < 2; mi++) {
            const int row0 = qb + warp * 32 + mi * 16 + crow;
            const int row1 = row0 + 8;
            if (masked) {
                const int colb = t * 64 + ccol;
#pragma unroll
                for (int nj = 0; nj < 8; nj++) {
                    const int c0 = colb + nj * 8;
                    if (c0 > row0)     S[mi][nj][0] = -1e30f;
                    if (c0 + 1 > row0) S[mi][nj][1] = -1e30f;
                    if (c0 > row1)     S[mi][nj][2] = -1e30f;
                    if (c0 + 1 > row1) S[mi][nj][3] = -1e30f;
                }
            }
            float mx0 = -1e30f, mx1 = -1e30f;
#pragma unroll
            for (int nj = 0; nj < 8; nj++) {
                mx0 = fmaxf(mx0, fmaxf(S[mi][nj][0], S[mi][nj][1]));
                mx1 = fmaxf(mx1, fmaxf(S[mi][nj][2], S[mi][nj][3]));
            }
            mx0 = fmaxf(mx0, __shfl_xor_sync(0xffffffff, mx0, 1));
            mx0 = fmaxf(mx0, __shfl_xor_sync(0xffffffff, mx0, 2));
            mx1 = fmaxf(mx1, __shfl_xor_sync(0xffffffff, mx1, 1));
            mx1 = fmaxf(mx1, __shfl_xor_sync(0xffffffff, mx1, 2));
            const float mn0 = fmaxf(m[mi][0], mx0);
            const float mn1 = fmaxf(m[mi][1], mx1);
            const float a0 = __expf(m[mi][0] - mn0);
            const float a1 = __expf(m[mi][1] - mn1);
            m[mi][0] = mn0; m[mi][1] = mn1;
            float rs0 = 0.f, rs1 = 0.f;
#pragma unroll
            for (int nj = 0; nj < 8; nj++) {
                S[mi][nj][0] = __expf(S[mi][nj][0] - mn0);
                S[mi][nj][1] = __expf(S[mi][nj][1] - mn0);
                S[mi][nj][2] = __expf(S[mi][nj][2] - mn1);
                S[mi][nj][3] = __expf(S[mi][nj][3] - mn1);
                rs0 += S[mi][nj][0] + S[mi][nj][1];
                rs1 += S[mi][nj][2] + S[mi][nj][3];
            }
            l[mi][0] = l[mi][0] * a0 + rs0;
            l[mi][1] = l[mi][1] * a1 + rs1;
#pragma unroll
            for (int nj = 0; nj < 8; nj++) {
                O[mi][nj][0] *= a0; O[mi][nj][1] *= a0;
                O[mi][nj][2] *= a1; O[mi][nj][3] *= a1;
            }
        }

        // ---- O += P V (3-term) --------------------------------------------
        const uint32_t vb = kb + 2 * AT_OP;
#pragma unroll
        for (int ks = 0; ks < 4; ks++) {
            uint32_t ph[2][4], pl[2][4];
#pragma unroll
            for (int mi = 0; mi < 2; mi++) {
                const float* sA = S[mi][2 * ks];
                const float* sB = S[mi][2 * ks + 1];
                splitpack(sA[0], sA[1], ph[mi][0], pl[mi][0]);
                splitpack(sA[2], sA[3], ph[mi][1], pl[mi][1]);
                splitpack(sB[0], sB[1], ph[mi][2], pl[mi][2]);
                splitpack(sB[2], sB[3], ph[mi][3], pl[mi][3]);
            }
#pragma unroll
            for (int nj2 = 0; nj2 < 4; nj2++) {
                const uint32_t ad = vb + (uint32_t)(ks * 16 + koffV) * AT_ROWB
                                    + (uint32_t)(nj2 * 16 + doffV) * 2;
                uint32_t vh0, vh1, vh2, vh3, vl0, vl1, vl2, vl3;
                LDSM_X4_T(vh0, vh1, vh2, vh3, ad);
                LDSM_X4_T(vl0, vl1, vl2, vl3, ad + AT_OP);
                uint32_t v0h[2] = {vh0, vh1}, v1h[2] = {vh2, vh3};
                uint32_t v0l[2] = {vl0, vl1}, v1l[2] = {vl2, vl3};
#pragma unroll
                for (int mi = 0; mi < 2; mi++) {
                    mma16816(O[mi][2 * nj2], ph[mi], v0h);
                    mma16816(O[mi][2 * nj2], ph[mi], v0l);
                    mma16816(O[mi][2 * nj2], pl[mi], v0h);
                    mma16816(O[mi][2 * nj2 + 1], ph[mi], v1h);
                    mma16816(O[mi][2 * nj2 + 1], ph[mi], v1l);
                    mma16816(O[mi][2 * nj2 + 1], pl[mi], v1h);
                }
            }
        }

        __syncthreads();                     // all warps done with stage t&1
        if (t + 2 < nt) KV_LOAD(t + 2, t & 1);
        CP_COMMIT();
    }

    // ---- epilogue: normalize, split hi/lo, store --------------------------
#pragma unroll
    for (int mi = 0; mi < 2; mi++) {
        float s0v = l[mi][0], s1v = l[mi][1];
        s0v += __shfl_xor_sync(0xffffffff, s0v, 1);
        s0v += __shfl_xor_sync(0xffffffff, s0v, 2);
        s1v += __shfl_xor_sync(0xffffffff, s1v, 1);
        s1v += __shfl_xor_sync(0xffffffff, s1v, 2);
        const float inv0 = 1.f / s0v, inv1 = 1.f / s1v;
        const int row0 = qb + warp * 32 + mi * 16 + crow;
        const size_t a0 = (rb + row0) * DDIM + h * 64;
        const size_t a1 = a0 + 8 * DDIM;
#pragma unroll
        for (int nj = 0; nj < 8; nj++) {
            const int col = nj * 8 + ccol;
            uint32_t hi, lo;
            splitpack(O[mi][nj][0] * inv0, O[mi][nj][1] * inv0, hi, lo);
            *(uint32_t*)(g_atthi + a0 + col) = hi;
            *(uint32_t*)(g_attlo + a0 + col) = lo;
            splitpack(O[mi][nj][2] * inv1, O[mi][nj][3] * inv1, hi, lo);
            *(uint32_t*)(g_atthi + a1 + col) = hi;
            *(uint32_t*)(g_attlo + a1 + col) = lo;
        }
    }
#undef KV_LOAD
}

// ---------------------------------------------------------------------------
// Inputs (metadata order): x, Wk, Wq, Wv, Wo. Output fp32 [8,1024,1024].
// ---------------------------------------------------------------------------
extern "C" void kernel_launch(void* const* d_in, const int* in_sizes, int n_in,
                              void* d_out, int out_size)
{
    const float* x  = (const float*)d_in[0];
    const float* Wk = (const float*)d_in[1];
    const float* Wq = (const float*)d_in[2];
    const float* Wv = (const float*)d_in[3];
    const float* Wo = (const float*)d_in[4];
    float* out = (float*)d_out;

    static int configured = 0;
    if (!configured) {
        cudaFuncSetAttribute(qkv_tc_kernel, cudaFuncAttributeMaxDynamicSharedMemorySize, SMEM_DYN);
        cudaFuncSetAttribute(out_tc_kernel, cudaFuncAttributeMaxDynamicSharedMemorySize, SMEM_DYN);
        cudaFuncSetAttribute(attn_tc_kernel, cudaFuncAttributeMaxDynamicSharedMemorySize, AT_SMEM);
        configured = 1;
    }

    cvt_x_kernel<<<8192, 256>>>((const float4*)x);
    cvt_w_kernel<<<dim3(1024, 1, 4), 256>>>((const float4*)Wk, (const float4*)Wq,
                                            (const float4*)Wv, (const float4*)Wo);

    qkv_tc_kernel<<<dim3(8, 64, 3), 256, SMEM_DYN>>>();

    attn_tc_kernel<<<dim3(8, 128), 128, AT_SMEM>>>();

    out_tc_kernel<<<dim3(8, 64), 256, SMEM_DYN>>>(out);
}

// round 5
// speedup vs baseline: 2.3905x; 1.0078x over previous
#include <cuda_runtime.h>
#include <cuda_bf16.h>
#include <math_constants.h>
#include <cstdint>

#define TDIM   1024
#define DDIM   1024
#define NBATCH 8
#define NHEADS 16
#define MROWS  (NBATCH * TDIM)   // 8192

// ---------------- scratch (__device__ globals) ------------------------------
__device__ __align__(256) __nv_bfloat16 g_xhi[MROWS * DDIM];
__device__ __align__(256) __nv_bfloat16 g_xlo[MROWS * DDIM];
__device__ __align__(256) __nv_bfloat16 g_qhi[MROWS * DDIM];
__device__ __align__(256) __nv_bfloat16 g_qlo[MROWS * DDIM];
__device__ __align__(256) __nv_bfloat16 g_khi[MROWS * DDIM];
__device__ __align__(256) __nv_bfloat16 g_klo[MROWS * DDIM];
__device__ __align__(256) __nv_bfloat16 g_vhi[MROWS * DDIM];
__device__ __align__(256) __nv_bfloat16 g_vlo[MROWS * DDIM];
__device__ __align__(256) __nv_bfloat16 g_atthi[MROWS * DDIM];
__device__ __align__(256) __nv_bfloat16 g_attlo[MROWS * DDIM];
__device__ __align__(256) __nv_bfloat16 g_wqhi[DDIM * DDIM];
__device__ __align__(256) __nv_bfloat16 g_wqlo[DDIM * DDIM];
__device__ __align__(256) __nv_bfloat16 g_wkhi[DDIM * DDIM];
__device__ __align__(256) __nv_bfloat16 g_wklo[DDIM * DDIM];
__device__ __align__(256) __nv_bfloat16 g_wvhi[DDIM * DDIM];
__device__ __align__(256) __nv_bfloat16 g_wvlo[DDIM * DDIM];
__device__ __align__(256) __nv_bfloat16 g_wohi[DDIM * DDIM];
__device__ __align__(256) __nv_bfloat16 g_wolo[DDIM * DDIM];

// ---------------- PTX helpers ----------------------------------------------
__device__ __forceinline__ uint32_t smem_u32(const void* p) {
    uint32_t a;
    asm("{ .reg .u64 t; cvta.to.shared.u64 t, %1; cvt.u32.u64 %0, t; }" : "=r"(a) : "l"(p));
    return a;
}
__device__ __forceinline__ void cp16(uint32_t dst, const void* src) {
    asm volatile("cp.async.cg.shared.global [%0], [%1], 16;" :: "r"(dst), "l"(src));
}
#define CP_COMMIT()  asm volatile("cp.async.commit_group;" ::: "memory")
#define CP_WAIT(n)   asm volatile("cp.async.wait_group %0;" :: "n"(n) : "memory")

#define LDSM_X4(r0, r1, r2, r3, a)                                                 \
    asm volatile("ldmatrix.sync.aligned.m8n8.x4.shared.b16 {%0,%1,%2,%3}, [%4];"   \
                 : "=r"(r0), "=r"(r1), "=r"(r2), "=r"(r3) : "r"(a))
#define LDSM_X4_T(r0, r1, r2, r3, a)                                               \
    asm volatile("ldmatrix.sync.aligned.m8n8.x4.trans.shared.b16 {%0,%1,%2,%3}, [%4];" \
                 : "=r"(r0), "=r"(r1), "=r"(r2), "=r"(r3) : "r"(a))

__device__ __forceinline__ void mma16816(float* c, const uint32_t* a, const uint32_t* b)
{
    asm volatile(
        "mma.sync.aligned.m16n8k16.row.col.f32.bf16.bf16.f32 "
        "{%0,%1,%2,%3}, {%4,%5,%6,%7}, {%8,%9}, {%0,%1,%2,%3};"
        : "+f"(c[0]), "+f"(c[1]), "+f"(c[2]), "+f"(c[3])
        : "r"(a[0]), "r"(a[1]), "r"(a[2]), "r"(a[3]), "r"(b[0]), "r"(b[1]));
}

__device__ __forceinline__ void splitpack(float a, float b, uint32_t& hi, uint32_t& lo)
{
    __nv_bfloat16 ha = __float2bfloat16(a), hb = __float2bfloat16(b);
    __nv_bfloat16 la = __float2bfloat16(a - __bfloat162float(ha));
    __nv_bfloat16 lb = __float2bfloat16(b - __bfloat162float(hb));
    __nv_bfloat162 H(ha, hb), L(la, lb);
    hi = *(uint32_t*)&H;
    lo = *(uint32_t*)&L;
}

// ---------------------------------------------------------------------------
// bf16 3-term split GEMM via mma.sync. CTA 128x128, 512 threads, 16 warps in
// 4x4, warp tile 32x32, K-chunk 32, 3-stage cp.async. Row stride 80B keeps
// ldmatrix phases conflict-free (16*(5r mod 8) slot permutation).
// MODE 0: fp32 C.  MODE 1: scale then split to bf16 hi/lo.
// ---------------------------------------------------------------------------
#define STRIDE 80
#define OPB    10240
#define STGB   (4 * OPB)
#define NSTG   3
#define SMEM_DYN (NSTG * STGB)     // 122880

template<int MODE>
__device__ __forceinline__ void bfmma_gemm(const __nv_bfloat16* __restrict__ Ahi,
                                           const __nv_bfloat16* __restrict__ Alo,
                                           const __nv_bfloat16* __restrict__ Bhi,
                                           const __nv_bfloat16* __restrict__ Blo,
                                           float* __restrict__ C,
                                           __nv_bfloat16* __restrict__ Chi,
                                           __nv_bfloat16* __restrict__ Clo,
                                           float scale)
{
    extern __shared__ char smraw[];
    const uint32_t s0 = smem_u32(smraw);

    const int tid  = threadIdx.x;
    const int warp = tid >> 5;
    const int lane = tid & 31;
    const int m0   = blockIdx.y * 128;
    const int n0   = blockIdx.x * 128;
    const int wm   = (warp >> 2) * 32;
    const int wn   = (warp & 3) * 32;

    const int op   = tid >> 7;           // 128 threads per operand
    const int t128 = tid & 127;
    const char* gbase;
    if (op == 0)      gbase = (const char*)(Ahi + (size_t)m0 * DDIM);
    else if (op == 1) gbase = (const char*)(Alo + (size_t)m0 * DDIM);
    else if (op == 2) gbase = (const char*)(Bhi + (size_t)n0 * DDIM);
    else              gbase = (const char*)(Blo + (size_t)n0 * DDIM);

#define LOAD_STAGE(kc, st)                                                     \
    {                                                                          \
        const uint32_t sb = s0 + (st) * STGB + op * OPB;                       \
        _Pragma("unroll")                                                      \
        for (int j = 0; j < 4; j++) {                                          \
            int id = t128 + (j << 7);                                          \
            int row = id >> 2, c = id & 3;                                     \
            cp16(sb + row * STRIDE + c * 16,                                   \
                 gbase + (size_t)row * 2048 + (kc) * 64 + c * 16);             \
        }                                                                      \
    }

    float acc[2][4][4];
#pragma unroll
    for (int i = 0; i < 2; i++)
#pragma unroll
        for (int j = 0; j < 4; j++)
#pragma unroll
            for (int r = 0; r < 4; r++) acc[i][j][r] = 0.f;

    LOAD_STAGE(0, 0); CP_COMMIT();
    LOAD_STAGE(1, 1); CP_COMMIT();

    const int arow_b = (lane & 15);
    const int ahalf  = (lane >> 4);

    for (int i = 0; i < 32; i++) {
        if (i < 30) { CP_WAIT(1); } else if (i == 30) { CP_WAIT(0); }
        __syncthreads();
        if (i < 30) { LOAD_STAGE(i + 2, (i + 2) % NSTG); CP_COMMIT(); }

        const uint32_t base = s0 + (i % NSTG) * STGB;
#pragma unroll
        for (int g = 0; g < 2; g++) {
            const uint32_t coff = (uint32_t)(2 * g + ahalf) * 16;
            uint32_t ah[2][4], al[2][4], bh[4][2], bl[4][2];
#pragma unroll
            for (int mi = 0; mi < 2; mi++) {
                const uint32_t ra = (uint32_t)(wm + mi * 16 + arow_b) * STRIDE + coff;
                LDSM_X4(ah[mi][0], ah[mi][1], ah[mi][2], ah[mi][3], base + ra);
                LDSM_X4(al[mi][0], al[mi][1], al[mi][2], al[mi][3], base + OPB + ra);
            }
#pragma unroll
            for (int jp = 0; jp < 2; jp++) {
                const uint32_t rbo = (uint32_t)(wn + jp * 16 + arow_b) * STRIDE + coff;
                uint32_t t0, t1, t2, t3;
                LDSM_X4(t0, t1, t2, t3, base + 2 * OPB + rbo);
                bh[2 * jp][0] = t0; bh[2 * jp][1] = t2;
                bh[2 * jp + 1][0] = t1; bh[2 * jp + 1][1] = t3;
                LDSM_X4(t0, t1, t2, t3, base + 3 * OPB + rbo);
                bl[2 * jp][0] = t0; bl[2 * jp][1] = t2;
                bl[2 * jp + 1][0] = t1; bl[2 * jp + 1][1] = t3;
            }
#pragma unroll
            for (int mi = 0; mi < 2; mi++)
#pragma unroll
                for (int nj = 0; nj < 4; nj++) {
                    mma16816(acc[mi][nj], ah[mi], bh[nj]);
                    mma16816(acc[mi][nj], ah[mi], bl[nj]);
                    mma16816(acc[mi][nj], al[mi], bh[nj]);
                }
        }
    }

    const int crow = lane >> 2;
    const int ccol = (lane & 3) * 2;
#pragma unroll
    for (int mi = 0; mi < 2; mi++)
#pragma unroll
        for (int nj = 0; nj < 4; nj++) {
            const size_t r0 = (size_t)(m0 + wm + mi * 16 + crow) * DDIM + (n0 + wn + nj * 8 + ccol);
            if (MODE == 0) {
                *(float2*)(C + r0) = make_float2(acc[mi][nj][0], acc[mi][nj][1]);
                *(float2*)(C + r0 + 8 * DDIM) = make_float2(acc[mi][nj][2], acc[mi][nj][3]);
            } else {
                uint32_t hi, lo;
                splitpack(acc[mi][nj][0] * scale, acc[mi][nj][1] * scale, hi, lo);
                *(uint32_t*)(Chi + r0) = hi;
                *(uint32_t*)(Clo + r0) = lo;
                splitpack(acc[mi][nj][2] * scale, acc[mi][nj][3] * scale, hi, lo);
                *(uint32_t*)(Chi + r0 + 8 * DDIM) = hi;
                *(uint32_t*)(Clo + r0 + 8 * DDIM) = lo;
            }
        }
#undef LOAD_STAGE
}

__global__ void __launch_bounds__(512, 1) qkv_tc_kernel()
{
    if (blockIdx.z == 0)                       // Q pre-scaled by 1/sqrt(64)
        bfmma_gemm<1>(g_xhi, g_xlo, g_wqhi, g_wqlo, nullptr, g_qhi, g_qlo, 0.125f);
    else if (blockIdx.z == 1)
        bfmma_gemm<1>(g_xhi, g_xlo, g_wkhi, g_wklo, nullptr, g_khi, g_klo, 1.0f);
    else
        bfmma_gemm<1>(g_xhi, g_xlo, g_wvhi, g_wvlo, nullptr, g_vhi, g_vlo, 1.0f);
}

__global__ void __launch_bounds__(512, 1) out_tc_kernel(float* __restrict__ out)
{
    bfmma_gemm<0>(g_atthi, g_attlo, g_wohi, g_wolo, out, nullptr, nullptr, 1.0f);
}

// ---------------------------------------------------------------------------
// fp32 -> bf16 hi/lo split conversions
// ---------------------------------------------------------------------------
__device__ __forceinline__ void split4(float4 v, __nv_bfloat162* hi, __nv_bfloat162* lo, int i2)
{
    uint32_t h0, l0, h1, l1;
    splitpack(v.x, v.y, h0, l0);
    splitpack(v.z, v.w, h1, l1);
    ((uint32_t*)hi)[i2] = h0; ((uint32_t*)hi)[i2 + 1] = h1;
    ((uint32_t*)lo)[i2] = l0; ((uint32_t*)lo)[i2 + 1] = l1;
}

__global__ void __launch_bounds__(256) cvt_x_kernel(const float4* __restrict__ src)
{
    int i = blockIdx.x * 256 + threadIdx.x;
    split4(src[i], (__nv_bfloat162*)g_xhi, (__nv_bfloat162*)g_xlo, 2 * i);
}

__global__ void __launch_bounds__(256) cvt_w_kernel(const float4* __restrict__ wk,
                                                    const float4* __restrict__ wq,
                                                    const float4* __restrict__ wv,
                                                    const float4* __restrict__ wo)
{
    int i = blockIdx.x * 256 + threadIdx.x;
    const float4* src;
    __nv_bfloat162 *hi, *lo;
    switch (blockIdx.z) {
        case 0:  src = wq; hi = (__nv_bfloat162*)g_wqhi; lo = (__nv_bfloat162*)g_wqlo; break;
        case 1:  src = wk; hi = (__nv_bfloat162*)g_wkhi; lo = (__nv_bfloat162*)g_wklo; break;
        case 2:  src = wv; hi = (__nv_bfloat162*)g_wvhi; lo = (__nv_bfloat162*)g_wvlo; break;
        default: src = wo; hi = (__nv_bfloat162*)g_wohi; lo = (__nv_bfloat162*)g_wolo; break;
    }
    split4(src[i], hi, lo, 2 * i);
}

// ---------------------------------------------------------------------------
// Tensor-core causal flash attention, bf16 3-term split, fp32 accum.
// CTA = 128 q-rows x one (b,h); 256 threads, 8 warps x 16 rows. KV tiles of
// 64 keys, double-buffered cp.async. Scores pre-scaled (Q *= 0.125 in proj).
// Row stride 144B -> conflict-free ldmatrix.
// ---------------------------------------------------------------------------
#define AT_ROWB  144
#define AT_OP    9216              // 64 * 144
#define AT_STG   (4 * AT_OP)       // khi, klo, vhi, vlo
#define AT_SMEM  (2 * AT_STG)      // 73728

__global__ void __launch_bounds__(256, 2) attn_tc_kernel()
{
    extern __shared__ char smraw[];
    const uint32_t s0 = smem_u32(smraw);
    const int tid  = threadIdx.x;
    const int warp = tid >> 5;
    const int lane = tid & 31;
    const int y    = 7 - (int)blockIdx.x;      // heavy blocks first
    const int bh   = blockIdx.y;
    const int b    = bh >> 4, h = bh & 15;
    const int qb   = y * 128;
    const int nt   = 2 * y + 2;                // KV tiles of 64
    const size_t rb = (size_t)b * TDIM;

    // ---- stage Q (hi/lo) 128x64 -> smem, then ldmatrix to regs -------------
    {
        const int op = tid >> 7, t128 = tid & 127;
        const __nv_bfloat16* src = (op ? g_qlo : g_qhi) + (rb + qb) * DDIM + h * 64;
        const uint32_t dst = s0 + op * 18432;
#pragma unroll
        for (int j = 0; j < 8; j++) {
            int id = t128 + (j << 7);
            int row = id >> 3, c = id & 7;
            cp16(dst + row * AT_ROWB + c * 16, src + (size_t)row * DDIM + c * 8);
        }
        CP_COMMIT(); CP_WAIT(0);
        __syncthreads();
    }

    const int l15 = lane & 15, lh = lane >> 4;
    uint32_t qh[4][4], ql[4][4];
#pragma unroll
    for (int ks = 0; ks < 4; ks++) {
        uint32_t ad = s0 + (uint32_t)(warp * 16 + l15) * AT_ROWB
                      + (uint32_t)(ks * 16 + lh * 8) * 2;
        LDSM_X4(qh[ks][0], qh[ks][1], qh[ks][2], qh[ks][3], ad);
        LDSM_X4(ql[ks][0], ql[ks][1], ql[ks][2], ql[ks][3], ad + 18432);
    }
    __syncthreads();   // Q smem region free before KV loads reuse it

    float O[8][4], m[2], l[2];
    m[0] = m[1] = -1e30f;
    l[0] = l[1] = 0.f;
#pragma unroll
    for (int nj = 0; nj < 8; nj++)
#pragma unroll
        for (int c = 0; c < 4; c++) O[nj][c] = 0.f;

    const int crow = lane >> 2, ccol = (lane & 3) * 2;

#define KV_LOAD(t, st)                                                              \
    {                                                                               \
        const int op = tid >> 6;                                                    \
        const int t64 = tid & 63;                                                   \
        const __nv_bfloat16* sc =                                                   \
            (op == 0 ? g_khi : op == 1 ? g_klo : op == 2 ? g_vhi : g_vlo)           \
            + (rb + (t) * 64) * DDIM + h * 64;                                      \
        const uint32_t ds = s0 + (st) * AT_STG + op * AT_OP;                        \
        _Pragma("unroll")                                                           \
        for (int j = 0; j < 8; j++) {                                               \
            int id = t64 + (j << 6);                                                \
            int row = id >> 3, c = id & 7;                                          \
            cp16(ds + row * AT_ROWB + c * 16, sc + (size_t)row * DDIM + c * 8);     \
        }                                                                           \
    }

    KV_LOAD(0, 0); CP_COMMIT();
    KV_LOAD(1, 1); CP_COMMIT();

    const int koffV = (lane & 7) + (((lane >> 3) & 1) << 3);
    const int doffV = (lane >> 4) << 3;

    for (int t = 0; t < nt; t++) {
        CP_WAIT(1);
        __syncthreads();
        const uint32_t kb = s0 + (t & 1) * AT_STG;

        // ---- S = Q K^T (3-term) -------------------------------------------
        float S[8][4];
#pragma unroll
        for (int nj = 0; nj < 8; nj++)
#pragma unroll
            for (int c = 0; c < 4; c++) S[nj][c] = 0.f;

#pragma unroll
        for (int ks = 0; ks < 4; ks++) {
#pragma unroll
            for (int nj2 = 0; nj2 < 4; nj2++) {
                const uint32_t ad = kb + (uint32_t)(nj2 * 16 + l15) * AT_ROWB
                                    + (uint32_t)(ks * 16 + lh * 8) * 2;
                uint32_t kh0, kh1, kh2, kh3, kl0, kl1, kl2, kl3;
                LDSM_X4(kh0, kh1, kh2, kh3, ad);
                LDSM_X4(kl0, kl1, kl2, kl3, ad + AT_OP);
                uint32_t b0h[2] = {kh0, kh2}, b1h[2] = {kh1, kh3};
                uint32_t b0l[2] = {kl0, kl2}, b1l[2] = {kl1, kl3};
                mma16816(S[2 * nj2], qh[ks], b0h);
                mma16816(S[2 * nj2], qh[ks], b0l);
                mma16816(S[2 * nj2], ql[ks], b0h);
                mma16816(S[2 * nj2 + 1], qh[ks], b1h);
                mma16816(S[2 * nj2 + 1], qh[ks], b1l);
                mma16816(S[2 * nj2 + 1], ql[ks], b1h);
            }
        }

        // ---- online softmax -----------------------------------------------
        const bool masked = (t >= nt - 2);
        {
            const int row0 = qb + warp * 16 + crow;
            const int row1 = row0 + 8;
            if (masked) {
                const int colb = t * 64 + ccol;
#pragma unroll
                for (int nj = 0; nj < 8; nj++) {
                    const int c0 = colb + nj * 8;
                    if (c0 > row0)     S[nj][0] = -1e30f;
                    if (c0 + 1 > row0) S[nj][1] = -1e30f;
                    if (c0 > row1)     S[nj][2] = -1e30f;
                    if (c0 + 1 > row1) S[nj][3] = -1e30f;
                }
            }
            float mx0 = -1e30f, mx1 = -1e30f;
#pragma unroll
            for (int nj = 0; nj < 8; nj++) {
                mx0 = fmaxf(mx0, fmaxf(S[nj][0], S[nj][1]));
                mx1 = fmaxf(mx1, fmaxf(S[nj][2], S[nj][3]));
            }
            mx0 = fmaxf(mx0, __shfl_xor_sync(0xffffffff, mx0, 1));
            mx0 = fmaxf(mx0, __shfl_xor_sync(0xffffffff, mx0, 2));
            mx1 = fmaxf(mx1, __shfl_xor_sync(0xffffffff, mx1, 1));
            mx1 = fmaxf(mx1, __shfl_xor_sync(0xffffffff, mx1, 2));
            const float mn0 = fmaxf(m[0], mx0);
            const float mn1 = fmaxf(m[1], mx1);
            const float a0 = __expf(m[0] - mn0);
            const float a1 = __expf(m[1] - mn1);
            m[0] = mn0; m[1] = mn1;
            float rs0 = 0.f, rs1 = 0.f;
#pragma unroll
            for (int nj = 0; nj < 8; nj++) {
                S[nj][0] = __expf(S[nj][0] - mn0);
                S[nj][1] = __expf(S[nj][1] - mn0);
                S[nj][2] = __expf(S[nj][2] - mn1);
                S[nj][3] = __expf(S[nj][3] - mn1);
                rs0 += S[nj][0] + S[nj][1];
                rs1 += S[nj][2] + S[nj][3];
            }
            l[0] = l[0] * a0 + rs0;
            l[1] = l[1] * a1 + rs1;
#pragma unroll
            for (int nj = 0; nj < 8; nj++) {
                O[nj][0] *= a0; O[nj][1] *= a0;
                O[nj][2] *= a1; O[nj][3] *= a1;
            }
        }

        // ---- O += P V (3-term) --------------------------------------------
        const uint32_t vb = kb + 2 * AT_OP;
#pragma unroll
        for (int ks = 0; ks < 4; ks++) {
            uint32_t ph[4], pl[4];
            {
                const float* sA = S[2 * ks];
                const float* sB = S[2 * ks + 1];
                splitpack(sA[0], sA[1], ph[0], pl[0]);
                splitpack(sA[2], sA[3], ph[1], pl[1]);
                splitpack(sB[0], sB[1], ph[2], pl[2]);
                splitpack(sB[2], sB[3], ph[3], pl[3]);
            }
#pragma unroll
            for (int nj2 = 0; nj2 < 4; nj2++) {
                const uint32_t ad = vb + (uint32_t)(ks * 16 + koffV) * AT_ROWB
                                    + (uint32_t)(nj2 * 16 + doffV) * 2;
                uint32_t vh0, vh1, vh2, vh3, vl0, vl1, vl2, vl3;
                LDSM_X4_T(vh0, vh1, vh2, vh3, ad);
                LDSM_X4_T(vl0, vl1, vl2, vl3, ad + AT_OP);
                uint32_t v0h[2] = {vh0, vh1}, v1h[2] = {vh2, vh3};
                uint32_t v0l[2] = {vl0, vl1}, v1l[2] = {vl2, vl3};
                mma16816(O[2 * nj2], ph, v0h);
                mma16816(O[2 * nj2], ph, v0l);
                mma16816(O[2 * nj2], pl, v0h);
                mma16816(O[2 * nj2 + 1], ph, v1h);
                mma16816(O[2 * nj2 + 1], ph, v1l);
                mma16816(O[2 * nj2 + 1], pl, v1h);
            }
        }

        __syncthreads();                     // all warps done with stage t&1
        if (t + 2 < nt) KV_LOAD(t + 2, t & 1);
        CP_COMMIT();
    }

    // ---- epilogue: normalize, split hi/lo, store --------------------------
    {
        float s0v = l[0], s1v = l[1];
        s0v += __shfl_xor_sync(0xffffffff, s0v, 1);
        s0v += __shfl_xor_sync(0xffffffff, s0v, 2);
        s1v += __shfl_xor_sync(0xffffffff, s1v, 1);
        s1v += __shfl_xor_sync(0xffffffff, s1v, 2);
        const float inv0 = 1.f / s0v, inv1 = 1.f / s1v;
        const int row0 = qb + warp * 16 + crow;
        const size_t a0 = (rb + row0) * DDIM + h * 64;
        const size_t a1 = a0 + 8 * DDIM;
#pragma unroll
        for (int nj = 0; nj < 8; nj++) {
            const int col = nj * 8 + ccol;
            uint32_t hi, lo;
            splitpack(O[nj][0] * inv0, O[nj][1] * inv0, hi, lo);
            *(uint32_t*)(g_atthi + a0 + col) = hi;
            *(uint32_t*)(g_attlo + a0 + col) = lo;
            splitpack(O[nj][2] * inv1, O[nj][3] * inv1, hi, lo);
            *(uint32_t*)(g_atthi + a1 + col) = hi;
            *(uint32_t*)(g_attlo + a1 + col) = lo;
        }
    }
#undef KV_LOAD
}

// ---------------------------------------------------------------------------
// Inputs (metadata order): x, Wk, Wq, Wv, Wo. Output fp32 [8,1024,1024].
// ---------------------------------------------------------------------------
extern "C" void kernel_launch(void* const* d_in, const int* in_sizes, int n_in,
                              void* d_out, int out_size)
{
    const float* x  = (const float*)d_in[0];
    const float* Wk = (const float*)d_in[1];
    const float* Wq = (const float*)d_in[2];
    const float* Wv = (const float*)d_in[3];
    const float* Wo = (const float*)d_in[4];
    float* out = (float*)d_out;

    static int configured = 0;
    if (!configured) {
        cudaFuncSetAttribute(qkv_tc_kernel, cudaFuncAttributeMaxDynamicSharedMemorySize, SMEM_DYN);
        cudaFuncSetAttribute(out_tc_kernel, cudaFuncAttributeMaxDynamicSharedMemorySize, SMEM_DYN);
        cudaFuncSetAttribute(attn_tc_kernel, cudaFuncAttributeMaxDynamicSharedMemorySize, AT_SMEM);
        configured = 1;
    }

    cvt_x_kernel<<<8192, 256>>>((const float4*)x);
    cvt_w_kernel<<<dim3(1024, 1, 4), 256>>>((const float4*)Wk, (const float4*)Wq,
                                            (const float4*)Wv, (const float4*)Wo);

    qkv_tc_kernel<<<dim3(8, 64, 3), 512, SMEM_DYN>>>();

    attn_tc_kernel<<<dim3(8, 128), 256, AT_SMEM>>>();

    out_tc_kernel<<<dim3(8, 64), 512, SMEM_DYN>>>(out);
}

// round 6
// speedup vs baseline: 3.3784x; 1.4132x over previous
#include <cuda_runtime.h>
#include <cuda_fp16.h>
#include <math_constants.h>
#include <cstdint>

#define TDIM   1024
#define DDIM   1024
#define NBATCH 8
#define NHEADS 16
#define MROWS  (NBATCH * TDIM)   // 8192

// ---------------- scratch (__device__ globals) ------------------------------
__device__ __align__(256) __half g_x1[MROWS * DDIM];
__device__ __align__(256) __half g_x2[MROWS * DDIM];
__device__ __align__(256) __half g_q1[MROWS * DDIM];
__device__ __align__(256) __half g_q2[MROWS * DDIM];
__device__ __align__(256) __half g_k [MROWS * DDIM];
__device__ __align__(256) __half g_v [MROWS * DDIM];
__device__ __align__(256) __half g_att1[MROWS * DDIM];
__device__ __align__(256) __half g_att2[MROWS * DDIM];
__device__ __align__(256) __half g_wq[DDIM * DDIM];
__device__ __align__(256) __half g_wk[DDIM * DDIM];
__device__ __align__(256) __half g_wv[DDIM * DDIM];
__device__ __align__(256) __half g_wo[DDIM * DDIM];

// ---------------- PTX helpers ----------------------------------------------
__device__ __forceinline__ uint32_t smem_u32(const void* p) {
    uint32_t a;
    asm("{ .reg .u64 t; cvta.to.shared.u64 t, %1; cvt.u32.u64 %0, t; }" : "=r"(a) : "l"(p));
    return a;
}
__device__ __forceinline__ void cp16(uint32_t dst, const void* src) {
    asm volatile("cp.async.cg.shared.global [%0], [%1], 16;" :: "r"(dst), "l"(src));
}
#define CP_COMMIT()  asm volatile("cp.async.commit_group;" ::: "memory")
#define CP_WAIT(n)   asm volatile("cp.async.wait_group %0;" :: "n"(n) : "memory")

#define LDSM_X4(r0, r1, r2, r3, a)                                                 \
    asm volatile("ldmatrix.sync.aligned.m8n8.x4.shared.b16 {%0,%1,%2,%3}, [%4];"   \
                 : "=r"(r0), "=r"(r1), "=r"(r2), "=r"(r3) : "r"(a))
#define LDSM_X4_T(r0, r1, r2, r3, a)                                               \
    asm volatile("ldmatrix.sync.aligned.m8n8.x4.trans.shared.b16 {%0,%1,%2,%3}, [%4];" \
                 : "=r"(r0), "=r"(r1), "=r"(r2), "=r"(r3) : "r"(a))

__device__ __forceinline__ void mma16816(float* c, const uint32_t* a, const uint32_t* b)
{
    asm volatile(
        "mma.sync.aligned.m16n8k16.row.col.f32.f16.f16.f32 "
        "{%0,%1,%2,%3}, {%4,%5,%6,%7}, {%8,%9}, {%0,%1,%2,%3};"
        : "+f"(c[0]), "+f"(c[1]), "+f"(c[2]), "+f"(c[3])
        : "r"(a[0]), "r"(a[1]), "r"(a[2]), "r"(a[3]), "r"(b[0]), "r"(b[1]));
}

// split a,b into two fp16 terms each, packed as (a,b) half2 words
__device__ __forceinline__ void splitpack_h(float a, float b, uint32_t& t1, uint32_t& t2)
{
    __half ha = __float2half_rn(a), hb = __float2half_rn(b);
    __half la = __float2half_rn(a - __half2float(ha));
    __half lb = __float2half_rn(b - __half2float(hb));
    __half2 H(ha, hb), L(la, lb);
    t1 = *(uint32_t*)&H;
    t2 = *(uint32_t*)&L;
}
__device__ __forceinline__ uint32_t pack_h(float a, float b)
{
    __half2 H(__float2half_rn(a), __float2half_rn(b));
    return *(uint32_t*)&H;
}

// ---------------------------------------------------------------------------
// fp16 2-term split GEMM via mma.sync: C = (A1 + A2) · B^T, fp32 accum.
// A split in two fp16 terms; B single fp16. CTA 128x128, 512 thr (16 warps
// 4x4, warp tile 32x32), K-chunk 32, 3-stage cp.async, row stride 80B
// (conflict-free ldmatrix slot permutation).
// MODE 0: fp32 C.  MODE 1: scale + split into two fp16 outs.  MODE 2: scale
// + single fp16 out.
// ---------------------------------------------------------------------------
#define STRIDE 80
#define OPB    10240               // 128 rows * 80B
#define STGB   (3 * OPB)           // A1, A2, B
#define NSTG   3
#define SMEM_DYN (NSTG * STGB)     // 92160

template<int MODE>
__device__ __forceinline__ void hmma_gemm(const __half* __restrict__ A1,
                                          const __half* __restrict__ A2,
                                          const __half* __restrict__ B,
                                          float* __restrict__ C,
                                          __half* __restrict__ C1,
                                          __half* __restrict__ C2,
                                          float scale)
{
    extern __shared__ char smraw[];
    const uint32_t s0 = smem_u32(smraw);

    const int tid  = threadIdx.x;
    const int warp = tid >> 5;
    const int lane = tid & 31;
    const int m0   = blockIdx.y * 128;
    const int n0   = blockIdx.x * 128;
    const int wm   = (warp >> 2) * 32;
    const int wn   = (warp & 3) * 32;

    const char* ga1 = (const char*)(A1 + (size_t)m0 * DDIM);
    const char* ga2 = (const char*)(A2 + (size_t)m0 * DDIM);
    const char* gb  = (const char*)(B  + (size_t)n0 * DDIM);
    // each thread owns one (row,c) slot, replicated across the 3 tiles
    const int lrow = tid >> 2, lc = tid & 3;
    const size_t goff = (size_t)lrow * 2048 + lc * 16;
    const uint32_t soff = (uint32_t)lrow * STRIDE + lc * 16;

#define LOAD_STAGE(kc, st)                                                     \
    {                                                                          \
        const uint32_t sb = s0 + (st) * STGB + soff;                           \
        const size_t go = goff + (kc) * 64;                                    \
        cp16(sb,           ga1 + go);                                          \
        cp16(sb + OPB,     ga2 + go);                                          \
        cp16(sb + 2 * OPB, gb  + go);                                          \
    }

    float acc[2][4][4];
#pragma unroll
    for (int i = 0; i < 2; i++)
#pragma unroll
        for (int j = 0; j < 4; j++)
#pragma unroll
            for (int r = 0; r < 4; r++) acc[i][j][r] = 0.f;

    LOAD_STAGE(0, 0); CP_COMMIT();
    LOAD_STAGE(1, 1); CP_COMMIT();

    const int arow_b = (lane & 15);
    const int ahalf  = (lane >> 4);

    for (int i = 0; i < 32; i++) {
        if (i < 30) { CP_WAIT(1); } else if (i == 30) { CP_WAIT(0); }
        __syncthreads();
        if (i < 30) { LOAD_STAGE(i + 2, (i + 2) % NSTG); CP_COMMIT(); }

        const uint32_t base = s0 + (i % NSTG) * STGB;
#pragma unroll
        for (int g = 0; g < 2; g++) {
            const uint32_t coff = (uint32_t)(2 * g + ahalf) * 16;
            uint32_t a1[2][4], a2[2][4], bf[4][2];
#pragma unroll
            for (int mi = 0; mi < 2; mi++) {
                const uint32_t ra = (uint32_t)(wm + mi * 16 + arow_b) * STRIDE + coff;
                LDSM_X4(a1[mi][0], a1[mi][1], a1[mi][2], a1[mi][3], base + ra);
                LDSM_X4(a2[mi][0], a2[mi][1], a2[mi][2], a2[mi][3], base + OPB + ra);
            }
#pragma unroll
            for (int jp = 0; jp < 2; jp++) {
                const uint32_t rbo = (uint32_t)(wn + jp * 16 + arow_b) * STRIDE + coff;
                uint32_t t0, t1, t2, t3;
                LDSM_X4(t0, t1, t2, t3, base + 2 * OPB + rbo);
                bf[2 * jp][0] = t0; bf[2 * jp][1] = t2;
                bf[2 * jp + 1][0] = t1; bf[2 * jp + 1][1] = t3;
            }
#pragma unroll
            for (int mi = 0; mi < 2; mi++)
#pragma unroll
                for (int nj = 0; nj < 4; nj++) {
                    mma16816(acc[mi][nj], a1[mi], bf[nj]);
                    mma16816(acc[mi][nj], a2[mi], bf[nj]);
                }
        }
    }

    const int crow = lane >> 2;
    const int ccol = (lane & 3) * 2;
#pragma unroll
    for (int mi = 0; mi < 2; mi++)
#pragma unroll
        for (int nj = 0; nj < 4; nj++) {
            const size_t r0 = (size_t)(m0 + wm + mi * 16 + crow) * DDIM + (n0 + wn + nj * 8 + ccol);
            if (MODE == 0) {
                *(float2*)(C + r0) = make_float2(acc[mi][nj][0], acc[mi][nj][1]);
                *(float2*)(C + r0 + 8 * DDIM) = make_float2(acc[mi][nj][2], acc[mi][nj][3]);
            } else if (MODE == 1) {
                uint32_t t1, t2;
                splitpack_h(acc[mi][nj][0] * scale, acc[mi][nj][1] * scale, t1, t2);
                *(uint32_t*)(C1 + r0) = t1;
                *(uint32_t*)(C2 + r0) = t2;
                splitpack_h(acc[mi][nj][2] * scale, acc[mi][nj][3] * scale, t1, t2);
                *(uint32_t*)(C1 + r0 + 8 * DDIM) = t1;
                *(uint32_t*)(C2 + r0 + 8 * DDIM) = t2;
            } else {
                *(uint32_t*)(C1 + r0) = pack_h(acc[mi][nj][0] * scale, acc[mi][nj][1] * scale);
                *(uint32_t*)(C1 + r0 + 8 * DDIM) = pack_h(acc[mi][nj][2] * scale, acc[mi][nj][3] * scale);
            }
        }
#undef LOAD_STAGE
}

__global__ void __launch_bounds__(512, 1) qkv_tc_kernel()
{
    if (blockIdx.z == 0)                       // Q pre-scaled by 1/sqrt(64), 2-term
        hmma_gemm<1>(g_x1, g_x2, g_wq, nullptr, g_q1, g_q2, 0.125f);
    else if (blockIdx.z == 1)
        hmma_gemm<2>(g_x1, g_x2, g_wk, nullptr, g_k, nullptr, 1.0f);
    else
        hmma_gemm<2>(g_x1, g_x2, g_wv, nullptr, g_v, nullptr, 1.0f);
}

__global__ void __launch_bounds__(512, 1) out_tc_kernel(float* __restrict__ out)
{
    hmma_gemm<0>(g_att1, g_att2, g_wo, out, nullptr, nullptr, 1.0f);
}

// ---------------------------------------------------------------------------
// conversions
// ---------------------------------------------------------------------------
__global__ void __launch_bounds__(256) cvt_x_kernel(const float4* __restrict__ src)
{
    int i = blockIdx.x * 256 + threadIdx.x;
    float4 v = src[i];
    uint32_t a1, a2, b1, b2;
    splitpack_h(v.x, v.y, a1, a2);
    splitpack_h(v.z, v.w, b1, b2);
    ((uint32_t*)g_x1)[2 * i] = a1; ((uint32_t*)g_x1)[2 * i + 1] = b1;
    ((uint32_t*)g_x2)[2 * i] = a2; ((uint32_t*)g_x2)[2 * i + 1] = b2;
}

__global__ void __launch_bounds__(256) cvt_w_kernel(const float4* __restrict__ wk,
                                                    const float4* __restrict__ wq,
                                                    const float4* __restrict__ wv,
                                                    const float4* __restrict__ wo)
{
    int i = blockIdx.x * 256 + threadIdx.x;
    const float4* src;
    __half* dst;
    switch (blockIdx.z) {
        case 0:  src = wq; dst = g_wq; break;
        case 1:  src = wk; dst = g_wk; break;
        case 2:  src = wv; dst = g_wv; break;
        default: src = wo; dst = g_wo; break;
    }
    float4 v = src[i];
    ((uint32_t*)dst)[2 * i]     = pack_h(v.x, v.y);
    ((uint32_t*)dst)[2 * i + 1] = pack_h(v.z, v.w);
}

// ---------------------------------------------------------------------------
// Tensor-core causal flash attention, fp16 2-term split, fp32 accum.
// CTA = 128 q-rows x one (b,h); 256 threads, 8 warps x 16 rows. Q split in 2
// fp16 terms; K,V single fp16. P split in 2 fp16 terms at PV. KV tiles of 64
// keys double-buffered cp.async. Scores pre-scaled (Q *= 0.125 in proj).
// Row stride 144B -> conflict-free ldmatrix.
// ---------------------------------------------------------------------------
#define AT_ROWB  144
#define AT_OP    9216              // 64 * 144
#define AT_STG   (2 * AT_OP)       // k, v
#define AT_SMEM  (2 * AT_STG)      // 36864 (also covers Q staging 2x18432)

__global__ void __launch_bounds__(256, 2) attn_tc_kernel()
{
    extern __shared__ char smraw[];
    const uint32_t s0 = smem_u32(smraw);
    const int tid  = threadIdx.x;
    const int warp = tid >> 5;
    const int lane = tid & 31;
    const int y    = 7 - (int)blockIdx.x;      // heavy blocks first
    const int bh   = blockIdx.y;
    const int b    = bh >> 4, h = bh & 15;
    const int qb   = y * 128;
    const int nt   = 2 * y + 2;                // KV tiles of 64
    const size_t rb = (size_t)b * TDIM;

    // ---- stage Q (2 terms) 128x64 -> smem, then ldmatrix to regs -----------
    {
#pragma unroll
        for (int j = 0; j < 8; j++) {
            int id = tid + (j << 8);            // 0..2047
            int t2 = id >> 10;                  // which term
            int within = id & 1023;
            int row = within >> 3, c = within & 7;
            const __half* src = (t2 ? g_q2 : g_q1) + (rb + qb) * DDIM + h * 64;
            cp16(s0 + t2 * 18432 + row * AT_ROWB + c * 16,
                 src + (size_t)row * DDIM + c * 8);
        }
        CP_COMMIT(); CP_WAIT(0);
        __syncthreads();
    }

    const int l15 = lane & 15, lh = lane >> 4;
    uint32_t q1[4][4], q2[4][4];
#pragma unroll
    for (int ks = 0; ks < 4; ks++) {
        uint32_t ad = s0 + (uint32_t)(warp * 16 + l15) * AT_ROWB
                      + (uint32_t)(ks * 16 + lh * 8) * 2;
        LDSM_X4(q1[ks][0], q1[ks][1], q1[ks][2], q1[ks][3], ad);
        LDSM_X4(q2[ks][0], q2[ks][1], q2[ks][2], q2[ks][3], ad + 18432);
    }
    __syncthreads();   // Q smem region free before KV loads reuse it

    float O[8][4], m[2], l[2];
    m[0] = m[1] = -1e30f;
    l[0] = l[1] = 0.f;
#pragma unroll
    for (int nj = 0; nj < 8; nj++)
#pragma unroll
        for (int c = 0; c < 4; c++) O[nj][c] = 0.f;

    const int crow = lane >> 2, ccol = (lane & 3) * 2;

#define KV_LOAD(t, st)                                                              \
    {                                                                               \
        const __half* kb_ = g_k + (rb + (t) * 64) * DDIM + h * 64;                  \
        const __half* vb_ = g_v + (rb + (t) * 64) * DDIM + h * 64;                  \
        const uint32_t ds = s0 + (st) * AT_STG;                                     \
        _Pragma("unroll")                                                           \
        for (int j = 0; j < 4; j++) {                                               \
            int id = tid + (j << 8);                                                \
            int tile = id >> 9;                                                     \
            int within = id & 511;                                                  \
            int row = within >> 3, c = within & 7;                                  \
            const __half* sc = tile ? vb_ : kb_;                                    \
            cp16(ds + tile * AT_OP + row * AT_ROWB + c * 16,                        \
                 sc + (size_t)row * DDIM + c * 8);                                  \
        }                                                                           \
    }

    KV_LOAD(0, 0); CP_COMMIT();
    KV_LOAD(1, 1); CP_COMMIT();

    const int koffV = (lane & 7) + (((lane >> 3) & 1) << 3);
    const int doffV = (lane >> 4) << 3;

    for (int t = 0; t < nt; t++) {
        CP_WAIT(1);
        __syncthreads();
        const uint32_t kb = s0 + (t & 1) * AT_STG;

        // ---- S = Q K^T (2-term) -------------------------------------------
        float S[8][4];
#pragma unroll
        for (int nj = 0; nj < 8; nj++)
#pragma unroll
            for (int c = 0; c < 4; c++) S[nj][c] = 0.f;

#pragma unroll
        for (int ks = 0; ks < 4; ks++) {
#pragma unroll
            for (int nj2 = 0; nj2 < 4; nj2++) {
                const uint32_t ad = kb + (uint32_t)(nj2 * 16 + l15) * AT_ROWB
                                    + (uint32_t)(ks * 16 + lh * 8) * 2;
                uint32_t k0, k1, k2, k3;
                LDSM_X4(k0, k1, k2, k3, ad);
                uint32_t b0[2] = {k0, k2}, b1[2] = {k1, k3};
                mma16816(S[2 * nj2], q1[ks], b0);
                mma16816(S[2 * nj2], q2[ks], b0);
                mma16816(S[2 * nj2 + 1], q1[ks], b1);
                mma16816(S[2 * nj2 + 1], q2[ks], b1);
            }
        }

        // ---- online softmax -----------------------------------------------
        const bool masked = (t >= nt - 2);
        {
            const int row0 = qb + warp * 16 + crow;
            const int row1 = row0 + 8;
            if (masked) {
                const int colb = t * 64 + ccol;
#pragma unroll
                for (int nj = 0; nj < 8; nj++) {
                    const int c0 = colb + nj * 8;
                    if (c0 > row0)     S[nj][0] = -1e30f;
                    if (c0 + 1 > row0) S[nj][1] = -1e30f;
                    if (c0 > row1)     S[nj][2] = -1e30f;
                    if (c0 + 1 > row1) S[nj][3] = -1e30f;
                }
            }
            float mx0 = -1e30f, mx1 = -1e30f;
#pragma unroll
            for (int nj = 0; nj < 8; nj++) {
                mx0 = fmaxf(mx0, fmaxf(S[nj][0], S[nj][1]));
                mx1 = fmaxf(mx1, fmaxf(S[nj][2], S[nj][3]));
            }
            mx0 = fmaxf(mx0, __shfl_xor_sync(0xffffffff, mx0, 1));
            mx0 = fmaxf(mx0, __shfl_xor_sync(0xffffffff, mx0, 2));
            mx1 = fmaxf(mx1, __shfl_xor_sync(0xffffffff, mx1, 1));
            mx1 = fmaxf(mx1, __shfl_xor_sync(0xffffffff, mx1, 2));
            const float mn0 = fmaxf(m[0], mx0);
            const float mn1 = fmaxf(m[1], mx1);
            const float a0 = __expf(m[0] - mn0);
            const float a1 = __expf(m[1] - mn1);
            m[0] = mn0; m[1] = mn1;
            float rs0 = 0.f, rs1 = 0.f;
#pragma unroll
            for (int nj = 0; nj < 8; nj++) {
                S[nj][0] = __expf(S[nj][0] - mn0);
                S[nj][1] = __expf(S[nj][1] - mn0);
                S[nj][2] = __expf(S[nj][2] - mn1);
                S[nj][3] = __expf(S[nj][3] - mn1);
                rs0 += S[nj][0] + S[nj][1];
                rs1 += S[nj][2] + S[nj][3];
            }
            l[0] = l[0] * a0 + rs0;
            l[1] = l[1] * a1 + rs1;
#pragma unroll
            for (int nj = 0; nj < 8; nj++) {
                O[nj][0] *= a0; O[nj][1] *= a0;
                O[nj][2] *= a1; O[nj][3] *= a1;
            }
        }

        // ---- O += P V (2-term P) ------------------------------------------
        const uint32_t vb = kb + AT_OP;
#pragma unroll
        for (int ks = 0; ks < 4; ks++) {
            uint32_t p1[4], p2[4];
            {
                const float* sA = S[2 * ks];
                const float* sB = S[2 * ks + 1];
                splitpack_h(sA[0], sA[1], p1[0], p2[0]);
                splitpack_h(sA[2], sA[3], p1[1], p2[1]);
                splitpack_h(sB[0], sB[1], p1[2], p2[2]);
                splitpack_h(sB[2], sB[3], p1[3], p2[3]);
            }
#pragma unroll
            for (int nj2 = 0; nj2 < 4; nj2++) {
                const uint32_t ad = vb + (uint32_t)(ks * 16 + koffV) * AT_ROWB
                                    + (uint32_t)(nj2 * 16 + doffV) * 2;
                uint32_t v0, v1, v2, v3;
                LDSM_X4_T(v0, v1, v2, v3, ad);
                uint32_t vp0[2] = {v0, v1}, vp1[2] = {v2, v3};
                mma16816(O[2 * nj2], p1, vp0);
                mma16816(O[2 * nj2], p2, vp0);
                mma16816(O[2 * nj2 + 1], p1, vp1);
                mma16816(O[2 * nj2 + 1], p2, vp1);
            }
        }

        __syncthreads();                     // all warps done with stage t&1
        if (t + 2 < nt) KV_LOAD(t + 2, t & 1);
        CP_COMMIT();
    }

    // ---- epilogue: normalize, 2-term split, store -------------------------
    {
        float s0v = l[0], s1v = l[1];
        s0v += __shfl_xor_sync(0xffffffff, s0v, 1);
        s0v += __shfl_xor_sync(0xffffffff, s0v, 2);
        s1v += __shfl_xor_sync(0xffffffff, s1v, 1);
        s1v += __shfl_xor_sync(0xffffffff, s1v, 2);
        const float inv0 = 1.f / s0v, inv1 = 1.f / s1v;
        const int row0 = qb + warp * 16 + crow;
        const size_t a0 = (rb + row0) * DDIM + h * 64;
        const size_t a1 = a0 + 8 * DDIM;
#pragma unroll
        for (int nj = 0; nj < 8; nj++) {
            const int col = nj * 8 + ccol;
            uint32_t t1, t2;
            splitpack_h(O[nj][0] * inv0, O[nj][1] * inv0, t1, t2);
            *(uint32_t*)(g_att1 + a0 + col) = t1;
            *(uint32_t*)(g_att2 + a0 + col) = t2;
            splitpack_h(O[nj][2] * inv1, O[nj][3] * inv1, t1, t2);
            *(uint32_t*)(g_att1 + a1 + col) = t1;
            *(uint32_t*)(g_att2 + a1 + col) = t2;
        }
    }
#undef KV_LOAD
}

// ---------------------------------------------------------------------------
// Inputs (metadata order): x, Wk, Wq, Wv, Wo. Output fp32 [8,1024,1024].
// ---------------------------------------------------------------------------
extern "C" void kernel_launch(void* const* d_in, const int* in_sizes, int n_in,
                              void* d_out, int out_size)
{
    const float* x  = (const float*)d_in[0];
    const float* Wk = (const float*)d_in[1];
    const float* Wq = (const float*)d_in[2];
    const float* Wv = (const float*)d_in[3];
    const float* Wo = (const float*)d_in[4];
    float* out = (float*)d_out;

    static int configured = 0;
    if (!configured) {
        cudaFuncSetAttribute(qkv_tc_kernel, cudaFuncAttributeMaxDynamicSharedMemorySize, SMEM_DYN);
        cudaFuncSetAttribute(out_tc_kernel, cudaFuncAttributeMaxDynamicSharedMemorySize, SMEM_DYN);
        cudaFuncSetAttribute(attn_tc_kernel, cudaFuncAttributeMaxDynamicSharedMemorySize, AT_SMEM);
        configured = 1;
    }

    cvt_x_kernel<<<8192, 256>>>((const float4*)x);
    cvt_w_kernel<<<dim3(1024, 1, 4), 256>>>((const float4*)Wk, (const float4*)Wq,
                                            (const float4*)Wv, (const float4*)Wo);

    qkv_tc_kernel<<<dim3(8, 64, 3), 512, SMEM_DYN>>>();

    attn_tc_kernel<<<dim3(8, 128), 256, AT_SMEM>>>();

    out_tc_kernel<<<dim3(8, 64), 512, SMEM_DYN>>>(out);
}

// round 7
// speedup vs baseline: 5.6846x; 1.6827x over previous
#include <cuda_runtime.h>
#include <cuda_fp16.h>
#include <math_constants.h>
#include <cstdint>

#define TDIM   1024
#define DDIM   1024
#define NBATCH 8
#define NHEADS 16
#define MROWS  (NBATCH * TDIM)   // 8192

// ---------------- scratch (__device__ globals) ------------------------------
__device__ __align__(256) __half g_x [MROWS * DDIM];
__device__ __align__(256) __half g_q1[MROWS * DDIM];
__device__ __align__(256) __half g_q2[MROWS * DDIM];
__device__ __align__(256) __half g_k [MROWS * DDIM];
__device__ __align__(256) __half g_v [MROWS * DDIM];
__device__ __align__(256) __half g_att[MROWS * DDIM];
__device__ __align__(256) __half g_wq[DDIM * DDIM];
__device__ __align__(256) __half g_wk[DDIM * DDIM];
__device__ __align__(256) __half g_wv[DDIM * DDIM];
__device__ __align__(256) __half g_wo[DDIM * DDIM];

// ---------------- PTX helpers ----------------------------------------------
__device__ __forceinline__ uint32_t smem_u32(const void* p) {
    uint32_t a;
    asm("{ .reg .u64 t; cvta.to.shared.u64 t, %1; cvt.u32.u64 %0, t; }" : "=r"(a) : "l"(p));
    return a;
}
__device__ __forceinline__ void cp16(uint32_t dst, const void* src) {
    asm volatile("cp.async.cg.shared.global [%0], [%1], 16;" :: "r"(dst), "l"(src));
}
#define CP_COMMIT()  asm volatile("cp.async.commit_group;" ::: "memory")
#define CP_WAIT(n)   asm volatile("cp.async.wait_group %0;" :: "n"(n) : "memory")

#define LDSM_X4(r0, r1, r2, r3, a)                                                 \
    asm volatile("ldmatrix.sync.aligned.m8n8.x4.shared.b16 {%0,%1,%2,%3}, [%4];"   \
                 : "=r"(r0), "=r"(r1), "=r"(r2), "=r"(r3) : "r"(a))
#define LDSM_X4_T(r0, r1, r2, r3, a)                                               \
    asm volatile("ldmatrix.sync.aligned.m8n8.x4.trans.shared.b16 {%0,%1,%2,%3}, [%4];" \
                 : "=r"(r0), "=r"(r1), "=r"(r2), "=r"(r3) : "r"(a))

__device__ __forceinline__ void mma16816(float* c, const uint32_t* a, const uint32_t* b)
{
    asm volatile(
        "mma.sync.aligned.m16n8k16.row.col.f32.f16.f16.f32 "
        "{%0,%1,%2,%3}, {%4,%5,%6,%7}, {%8,%9}, {%0,%1,%2,%3};"
        : "+f"(c[0]), "+f"(c[1]), "+f"(c[2]), "+f"(c[3])
        : "r"(a[0]), "r"(a[1]), "r"(a[2]), "r"(a[3]), "r"(b[0]), "r"(b[1]));
}

__device__ __forceinline__ void splitpack_h(float a, float b, uint32_t& t1, uint32_t& t2)
{
    __half ha = __float2half_rn(a), hb = __float2half_rn(b);
    __half la = __float2half_rn(a - __half2float(ha));
    __half lb = __float2half_rn(b - __half2float(hb));
    __half2 H(ha, hb), L(la, lb);
    t1 = *(uint32_t*)&H;
    t2 = *(uint32_t*)&L;
}
__device__ __forceinline__ uint32_t pack_h(float a, float b)
{
    __half2 H(__float2half_rn(a), __float2half_rn(b));
    return *(uint32_t*)&H;
}

// ---------------------------------------------------------------------------
// fp16 GEMM via mma.sync: C = A · B^T, fp32 accum, single-term operands.
// CTA 128x128, 512 thr (16 warps 4x4, warp tile 32x32), K-chunk 32, 3-stage
// cp.async, row stride 80B (conflict-free ldmatrix slot permutation).
// MODE 0: fp32 C.  MODE 1: scale + split into two fp16 outs (for Q).
// MODE 2: scale + single fp16 out.
// ---------------------------------------------------------------------------
#define STRIDE 80
#define OPB    10240               // 128 rows * 80B
#define STGB   (2 * OPB)           // A, B
#define NSTG   3
#define SMEM_DYN (NSTG * STGB)     // 61440

template<int MODE>
__device__ __forceinline__ void hmma_gemm(const __half* __restrict__ A,
                                          const __half* __restrict__ B,
                                          float* __restrict__ C,
                                          __half* __restrict__ C1,
                                          __half* __restrict__ C2,
                                          float scale)
{
    extern __shared__ char smraw[];
    const uint32_t s0 = smem_u32(smraw);

    const int tid  = threadIdx.x;
    const int warp = tid >> 5;
    const int lane = tid & 31;
    const int m0   = blockIdx.y * 128;
    const int n0   = blockIdx.x * 128;
    const int wm   = (warp >> 2) * 32;
    const int wn   = (warp & 3) * 32;

    const char* ga = (const char*)(A + (size_t)m0 * DDIM);
    const char* gb = (const char*)(B + (size_t)n0 * DDIM);
    const int lrow = tid >> 2, lc = tid & 3;
    const size_t goff = (size_t)lrow * 2048 + lc * 16;
    const uint32_t soff = (uint32_t)lrow * STRIDE + lc * 16;

#define LOAD_STAGE(kc, st)                                                     \
    {                                                                          \
        const uint32_t sb = s0 + (st) * STGB + soff;                           \
        const size_t go = goff + (kc) * 64;                                    \
        cp16(sb,       ga + go);                                               \
        cp16(sb + OPB, gb + go);                                               \
    }

    float acc[2][4][4];
#pragma unroll
    for (int i = 0; i < 2; i++)
#pragma unroll
        for (int j = 0; j < 4; j++)
#pragma unroll
            for (int r = 0; r < 4; r++) acc[i][j][r] = 0.f;

    LOAD_STAGE(0, 0); CP_COMMIT();
    LOAD_STAGE(1, 1); CP_COMMIT();

    const int arow_b = (lane & 15);
    const int ahalf  = (lane >> 4);

    for (int i = 0; i < 32; i++) {
        if (i < 30) { CP_WAIT(1); } else if (i == 30) { CP_WAIT(0); }
        __syncthreads();
        if (i < 30) { LOAD_STAGE(i + 2, (i + 2) % NSTG); CP_COMMIT(); }

        const uint32_t base = s0 + (i % NSTG) * STGB;
#pragma unroll
        for (int g = 0; g < 2; g++) {
            const uint32_t coff = (uint32_t)(2 * g + ahalf) * 16;
            uint32_t af[2][4], bf[4][2];
#pragma unroll
            for (int mi = 0; mi < 2; mi++) {
                const uint32_t ra = (uint32_t)(wm + mi * 16 + arow_b) * STRIDE + coff;
                LDSM_X4(af[mi][0], af[mi][1], af[mi][2], af[mi][3], base + ra);
            }
#pragma unroll
            for (int jp = 0; jp < 2; jp++) {
                const uint32_t rbo = (uint32_t)(wn + jp * 16 + arow_b) * STRIDE + coff;
                uint32_t t0, t1, t2, t3;
                LDSM_X4(t0, t1, t2, t3, base + OPB + rbo);
                bf[2 * jp][0] = t0; bf[2 * jp][1] = t2;
                bf[2 * jp + 1][0] = t1; bf[2 * jp + 1][1] = t3;
            }
#pragma unroll
            for (int mi = 0; mi < 2; mi++)
#pragma unroll
                for (int nj = 0; nj < 4; nj++)
                    mma16816(acc[mi][nj], af[mi], bf[nj]);
        }
    }

    const int crow = lane >> 2;
    const int ccol = (lane & 3) * 2;
#pragma unroll
    for (int mi = 0; mi < 2; mi++)
#pragma unroll
        for (int nj = 0; nj < 4; nj++) {
            const size_t r0 = (size_t)(m0 + wm + mi * 16 + crow) * DDIM + (n0 + wn + nj * 8 + ccol);
            if (MODE == 0) {
                *(float2*)(C + r0) = make_float2(acc[mi][nj][0], acc[mi][nj][1]);
                *(float2*)(C + r0 + 8 * DDIM) = make_float2(acc[mi][nj][2], acc[mi][nj][3]);
            } else if (MODE == 1) {
                uint32_t t1, t2;
                splitpack_h(acc[mi][nj][0] * scale, acc[mi][nj][1] * scale, t1, t2);
                *(uint32_t*)(C1 + r0) = t1;
                *(uint32_t*)(C2 + r0) = t2;
                splitpack_h(acc[mi][nj][2] * scale, acc[mi][nj][3] * scale, t1, t2);
                *(uint32_t*)(C1 + r0 + 8 * DDIM) = t1;
                *(uint32_t*)(C2 + r0 + 8 * DDIM) = t2;
            } else {
                *(uint32_t*)(C1 + r0) = pack_h(acc[mi][nj][0] * scale, acc[mi][nj][1] * scale);
                *(uint32_t*)(C1 + r0 + 8 * DDIM) = pack_h(acc[mi][nj][2] * scale, acc[mi][nj][3] * scale);
            }
        }
#undef LOAD_STAGE
}

__global__ void __launch_bounds__(512, 1) qkv_tc_kernel()
{
    if (blockIdx.z == 0)                       // Q pre-scaled by 1/sqrt(64), 2-term out
        hmma_gemm<1>(g_x, g_wq, nullptr, g_q1, g_q2, 0.125f);
    else if (blockIdx.z == 1)
        hmma_gemm<2>(g_x, g_wk, nullptr, g_k, nullptr, 1.0f);
    else
        hmma_gemm<2>(g_x, g_wv, nullptr, g_v, nullptr, 1.0f);
}

__global__ void __launch_bounds__(512, 1) out_tc_kernel(float* __restrict__ out)
{
    hmma_gemm<0>(g_att, g_wo, out, nullptr, nullptr, 1.0f);
}

// ---------------------------------------------------------------------------
// conversions (single fp16)
// ---------------------------------------------------------------------------
__global__ void __launch_bounds__(256) cvt_x_kernel(const float4* __restrict__ src)
{
    int i = blockIdx.x * 256 + threadIdx.x;
    float4 v = src[i];
    ((uint32_t*)g_x)[2 * i]     = pack_h(v.x, v.y);
    ((uint32_t*)g_x)[2 * i + 1] = pack_h(v.z, v.w);
}

__global__ void __launch_bounds__(256) cvt_w_kernel(const float4* __restrict__ wk,
                                                    const float4* __restrict__ wq,
                                                    const float4* __restrict__ wv,
                                                    const float4* __restrict__ wo)
{
    int i = blockIdx.x * 256 + threadIdx.x;
    const float4* src;
    __half* dst;
    switch (blockIdx.z) {
        case 0:  src = wq; dst = g_wq; break;
        case 1:  src = wk; dst = g_wk; break;
        case 2:  src = wv; dst = g_wv; break;
        default: src = wo; dst = g_wo; break;
    }
    float4 v = src[i];
    ((uint32_t*)dst)[2 * i]     = pack_h(v.x, v.y);
    ((uint32_t*)dst)[2 * i + 1] = pack_h(v.z, v.w);
}

// ---------------------------------------------------------------------------
// Tensor-core causal flash attention, fp32 accum. Q split 2-term fp16,
// K,V single fp16, P split 2-term fp16. CTA = 128 q-rows x one (b,h);
// 256 threads, 8 warps x 16 rows. KV tiles of 64 keys double-buffered
// cp.async. Scores pre-scaled (Q *= 0.125 in proj). Row stride 144B.
// Epilogue emits single fp16 att (O-proj A-side is single-term).
// ---------------------------------------------------------------------------
#define AT_ROWB  144
#define AT_OP    9216              // 64 * 144
#define AT_STG   (2 * AT_OP)       // k, v
#define AT_SMEM  (2 * AT_STG)      // 36864 (also covers Q staging 2x18432)

__global__ void __launch_bounds__(256, 2) attn_tc_kernel()
{
    extern __shared__ char smraw[];
    const uint32_t s0 = smem_u32(smraw);
    const int tid  = threadIdx.x;
    const int warp = tid >> 5;
    const int lane = tid & 31;
    const int y    = 7 - (int)blockIdx.x;      // heavy blocks first
    const int bh   = blockIdx.y;
    const int b    = bh >> 4, h = bh & 15;
    const int qb   = y * 128;
    const int nt   = 2 * y + 2;                // KV tiles of 64
    const size_t rb = (size_t)b * TDIM;

    // ---- stage Q (2 terms) 128x64 -> smem, then ldmatrix to regs -----------
    {
#pragma unroll
        for (int j = 0; j < 8; j++) {
            int id = tid + (j << 8);            // 0..2047
            int t2 = id >> 10;                  // which term
            int within = id & 1023;
            int row = within >> 3, c = within & 7;
            const __half* src = (t2 ? g_q2 : g_q1) + (rb + qb) * DDIM + h * 64;
            cp16(s0 + t2 * 18432 + row * AT_ROWB + c * 16,
                 src + (size_t)row * DDIM + c * 8);
        }
        CP_COMMIT(); CP_WAIT(0);
        __syncthreads();
    }

    const int l15 = lane & 15, lh = lane >> 4;
    uint32_t q1[4][4], q2[4][4];
#pragma unroll
    for (int ks = 0; ks < 4; ks++) {
        uint32_t ad = s0 + (uint32_t)(warp * 16 + l15) * AT_ROWB
                      + (uint32_t)(ks * 16 + lh * 8) * 2;
        LDSM_X4(q1[ks][0], q1[ks][1], q1[ks][2], q1[ks][3], ad);
        LDSM_X4(q2[ks][0], q2[ks][1], q2[ks][2], q2[ks][3], ad + 18432);
    }
    __syncthreads();   // Q smem region free before KV loads reuse it

    float O[8][4], m[2], l[2];
    m[0] = m[1] = -1e30f;
    l[0] = l[1] = 0.f;
#pragma unroll
    for (int nj = 0; nj < 8; nj++)
#pragma unroll
        for (int c = 0; c < 4; c++) O[nj][c] = 0.f;

    const int crow = lane >> 2, ccol = (lane & 3) * 2;

#define KV_LOAD(t, st)                                                              \
    {                                                                               \
        const __half* kb_ = g_k + (rb + (t) * 64) * DDIM + h * 64;                  \
        const __half* vb_ = g_v + (rb + (t) * 64) * DDIM + h * 64;                  \
        const uint32_t ds = s0 + (st) * AT_STG;                                     \
        _Pragma("unroll")                                                           \
        for (int j = 0; j < 4; j++) {                                               \
            int id = tid + (j << 8);                                                \
            int tile = id >> 9;                                                     \
            int within = id & 511;                                                  \
            int row = within >> 3, c = within & 7;                                  \
            const __half* sc = tile ? vb_ : kb_;                                    \
            cp16(ds + tile * AT_OP + row * AT_ROWB + c * 16,                        \
                 sc + (size_t)row * DDIM + c * 8);                                  \
        }                                                                           \
    }

    KV_LOAD(0, 0); CP_COMMIT();
    KV_LOAD(1, 1); CP_COMMIT();

    const int koffV = (lane & 7) + (((lane >> 3) & 1) << 3);
    const int doffV = (lane >> 4) << 3;

    for (int t = 0; t < nt; t++) {
        CP_WAIT(1);
        __syncthreads();
        const uint32_t kb = s0 + (t & 1) * AT_STG;

        // ---- S = Q K^T (2-term Q) -----------------------------------------
        float S[8][4];
#pragma unroll
        for (int nj = 0; nj < 8; nj++)
#pragma unroll
            for (int c = 0; c < 4; c++) S[nj][c] = 0.f;

#pragma unroll
        for (int ks = 0; ks < 4; ks++) {
#pragma unroll
            for (int nj2 = 0; nj2 < 4; nj2++) {
                const uint32_t ad = kb + (uint32_t)(nj2 * 16 + l15) * AT_ROWB
                                    + (uint32_t)(ks * 16 + lh * 8) * 2;
                uint32_t k0, k1, k2, k3;
                LDSM_X4(k0, k1, k2, k3, ad);
                uint32_t b0[2] = {k0, k2}, b1[2] = {k1, k3};
                mma16816(S[2 * nj2], q1[ks], b0);
                mma16816(S[2 * nj2], q2[ks], b0);
                mma16816(S[2 * nj2 + 1], q1[ks], b1);
                mma16816(S[2 * nj2 + 1], q2[ks], b1);
            }
        }

        // ---- online softmax -----------------------------------------------
        const bool masked = (t >= nt - 2);
        {
            const int row0 = qb + warp * 16 + crow;
            const int row1 = row0 + 8;
            if (masked) {
                const int colb = t * 64 + ccol;
#pragma unroll
                for (int nj = 0; nj < 8; nj++) {
                    const int c0 = colb + nj * 8;
                    if (c0 > row0)     S[nj][0] = -1e30f;
                    if (c0 + 1 > row0) S[nj][1] = -1e30f;
                    if (c0 > row1)     S[nj][2] = -1e30f;
                    if (c0 + 1 > row1) S[nj][3] = -1e30f;
                }
            }
            float mx0 = -1e30f, mx1 = -1e30f;
#pragma unroll
            for (int nj = 0; nj < 8; nj++) {
                mx0 = fmaxf(mx0, fmaxf(S[nj][0], S[nj][1]));
                mx1 = fmaxf(mx1, fmaxf(S[nj][2], S[nj][3]));
            }
            mx0 = fmaxf(mx0, __shfl_xor_sync(0xffffffff, mx0, 1));
            mx0 = fmaxf(mx0, __shfl_xor_sync(0xffffffff, mx0, 2));
            mx1 = fmaxf(mx1, __shfl_xor_sync(0xffffffff, mx1, 1));
            mx1 = fmaxf(mx1, __shfl_xor_sync(0xffffffff, mx1, 2));
            const float mn0 = fmaxf(m[0], mx0);
            const float mn1 = fmaxf(m[1], mx1);
            const float a0 = __expf(m[0] - mn0);
            const float a1 = __expf(m[1] - mn1);
            m[0] = mn0; m[1] = mn1;
            float rs0 = 0.f, rs1 = 0.f;
#pragma unroll
            for (int nj = 0; nj < 8; nj++) {
                S[nj][0] = __expf(S[nj][0] - mn0);
                S[nj][1] = __expf(S[nj][1] - mn0);
                S[nj][2] = __expf(S[nj][2] - mn1);
                S[nj][3] = __expf(S[nj][3] - mn1);
                rs0 += S[nj][0] + S[nj][1];
                rs1 += S[nj][2] + S[nj][3];
            }
            l[0] = l[0] * a0 + rs0;
            l[1] = l[1] * a1 + rs1;
#pragma unroll
            for (int nj = 0; nj < 8; nj++) {
                O[nj][0] *= a0; O[nj][1] *= a0;
                O[nj][2] *= a1; O[nj][3] *= a1;
            }
        }

        // ---- O += P V (2-term P) ------------------------------------------
        const uint32_t vb = kb + AT_OP;
#pragma unroll
        for (int ks = 0; ks < 4; ks++) {
            uint32_t p1[4], p2[4];
            {
                const float* sA = S[2 * ks];
                const float* sB = S[2 * ks + 1];
                splitpack_h(sA[0], sA[1], p1[0], p2[0]);
                splitpack_h(sA[2], sA[3], p1[1], p2[1]);
                splitpack_h(sB[0], sB[1], p1[2], p2[2]);
                splitpack_h(sB[2], sB[3], p1[3], p2[3]);
            }
#pragma unroll
            for (int nj2 = 0; nj2 < 4; nj2++) {
                const uint32_t ad = vb + (uint32_t)(ks * 16 + koffV) * AT_ROWB
                                    + (uint32_t)(nj2 * 16 + doffV) * 2;
                uint32_t v0, v1, v2, v3;
                LDSM_X4_T(v0, v1, v2, v3, ad);
                uint32_t vp0[2] = {v0, v1}, vp1[2] = {v2, v3};
                mma16816(O[2 * nj2], p1, vp0);
                mma16816(O[2 * nj2], p2, vp0);
                mma16816(O[2 * nj2 + 1], p1, vp1);
                mma16816(O[2 * nj2 + 1], p2, vp1);
            }
        }

        __syncthreads();                     // all warps done with stage t&1
        if (t + 2 < nt) KV_LOAD(t + 2, t & 1);
        CP_COMMIT();
    }

    // ---- epilogue: normalize, store single fp16 ---------------------------
    {
        float s0v = l[0], s1v = l[1];
        s0v += __shfl_xor_sync(0xffffffff, s0v, 1);
        s0v += __shfl_xor_sync(0xffffffff, s0v, 2);
        s1v += __shfl_xor_sync(0xffffffff, s1v, 1);
        s1v += __shfl_xor_sync(0xffffffff, s1v, 2);
        const float inv0 = 1.f / s0v, inv1 = 1.f / s1v;
        const int row0 = qb + warp * 16 + crow;
        const size_t a0 = (rb + row0) * DDIM + h * 64;
        const size_t a1 = a0 + 8 * DDIM;
#pragma unroll
        for (int nj = 0; nj < 8; nj++) {
            const int col = nj * 8 + ccol;
            *(uint32_t*)(g_att + a0 + col) = pack_h(O[nj][0] * inv0, O[nj][1] * inv0);
            *(uint32_t*)(g_att + a1 + col) = pack_h(O[nj][2] * inv1, O[nj][3] * inv1);
        }
    }
#undef KV_LOAD
}

// ---------------------------------------------------------------------------
// Inputs (metadata order): x, Wk, Wq, Wv, Wo. Output fp32 [8,1024,1024].
// ---------------------------------------------------------------------------
extern "C" void kernel_launch(void* const* d_in, const int* in_sizes, int n_in,
                              void* d_out, int out_size)
{
    const float* x  = (const float*)d_in[0];
    const float* Wk = (const float*)d_in[1];
    const float* Wq = (const float*)d_in[2];
    const float* Wv = (const float*)d_in[3];
    const float* Wo = (const float*)d_in[4];
    float* out = (float*)d_out;

    static int configured = 0;
    if (!configured) {
        cudaFuncSetAttribute(qkv_tc_kernel, cudaFuncAttributeMaxDynamicSharedMemorySize, SMEM_DYN);
        cudaFuncSetAttribute(out_tc_kernel, cudaFuncAttributeMaxDynamicSharedMemorySize, SMEM_DYN);
        cudaFuncSetAttribute(attn_tc_kernel, cudaFuncAttributeMaxDynamicSharedMemorySize, AT_SMEM);
        configured = 1;
    }

    cvt_x_kernel<<<8192, 256>>>((const float4*)x);
    cvt_w_kernel<<<dim3(1024, 1, 4), 256>>>((const float4*)Wk, (const float4*)Wq,
                                            (const float4*)Wv, (const float4*)Wo);

    qkv_tc_kernel<<<dim3(8, 64, 3), 512, SMEM_DYN>>>();

    attn_tc_kernel<<<dim3(8, 128), 256, AT_SMEM>>>();

    out_tc_kernel<<<dim3(8, 64), 512, SMEM_DYN>>>(out);
}

// round 8
// speedup vs baseline: 6.5961x; 1.1603x over previous
#include <cuda_runtime.h>
#include <cuda_fp16.h>
#include <math_constants.h>
#include <cstdint>

#define TDIM   1024
#define DDIM   1024
#define NBATCH 8
#define NHEADS 16
#define MROWS  (NBATCH * TDIM)   // 8192

// ---------------- scratch (__device__ globals) ------------------------------
__device__ __align__(256) __half g_x [MROWS * DDIM];
__device__ __align__(256) __half g_q [MROWS * DDIM];
__device__ __align__(256) __half g_k [MROWS * DDIM];
__device__ __align__(256) __half g_v [MROWS * DDIM];
__device__ __align__(256) __half g_att[MROWS * DDIM];
__device__ __align__(256) __half g_wq[DDIM * DDIM];
__device__ __align__(256) __half g_wk[DDIM * DDIM];
__device__ __align__(256) __half g_wv[DDIM * DDIM];
__device__ __align__(256) __half g_wo[DDIM * DDIM];

// ---------------- PTX helpers ----------------------------------------------
__device__ __forceinline__ uint32_t smem_u32(const void* p) {
    uint32_t a;
    asm("{ .reg .u64 t; cvta.to.shared.u64 t, %1; cvt.u32.u64 %0, t; }" : "=r"(a) : "l"(p));
    return a;
}
__device__ __forceinline__ void cp16(uint32_t dst, const void* src) {
    asm volatile("cp.async.cg.shared.global [%0], [%1], 16;" :: "r"(dst), "l"(src));
}
#define CP_COMMIT()  asm volatile("cp.async.commit_group;" ::: "memory")
#define CP_WAIT(n)   asm volatile("cp.async.wait_group %0;" :: "n"(n) : "memory")

#define LDSM_X4(r0, r1, r2, r3, a)                                                 \
    asm volatile("ldmatrix.sync.aligned.m8n8.x4.shared.b16 {%0,%1,%2,%3}, [%4];"   \
                 : "=r"(r0), "=r"(r1), "=r"(r2), "=r"(r3) : "r"(a))
#define LDSM_X4_T(r0, r1, r2, r3, a)                                               \
    asm volatile("ldmatrix.sync.aligned.m8n8.x4.trans.shared.b16 {%0,%1,%2,%3}, [%4];" \
                 : "=r"(r0), "=r"(r1), "=r"(r2), "=r"(r3) : "r"(a))

__device__ __forceinline__ void mma16816(float* c, const uint32_t* a, const uint32_t* b)
{
    asm volatile(
        "mma.sync.aligned.m16n8k16.row.col.f32.f16.f16.f32 "
        "{%0,%1,%2,%3}, {%4,%5,%6,%7}, {%8,%9}, {%0,%1,%2,%3};"
        : "+f"(c[0]), "+f"(c[1]), "+f"(c[2]), "+f"(c[3])
        : "r"(a[0]), "r"(a[1]), "r"(a[2]), "r"(a[3]), "r"(b[0]), "r"(b[1]));
}

__device__ __forceinline__ uint32_t pack_h(float a, float b)
{
    __half2 H(__float2half_rn(a), __float2half_rn(b));
    return *(uint32_t*)&H;
}

// ---------------------------------------------------------------------------
// fp16 GEMM via mma.sync: C = A · B^T, fp32 accum, single-term operands.
// CTA 128x128, 512 thr (16 warps 4x4, warp tile 32x32), K-chunk 32, 3-stage
// cp.async, row stride 80B (conflict-free ldmatrix slot permutation).
// MODE 0: fp32 C.  MODE 2: scale + single fp16 out.
// ---------------------------------------------------------------------------
#define STRIDE 80
#define OPB    10240               // 128 rows * 80B
#define STGB   (2 * OPB)           // A, B
#define NSTG   3
#define SMEM_DYN (NSTG * STGB)     // 61440

template<int MODE>
__device__ __forceinline__ void hmma_gemm(const __half* __restrict__ A,
                                          const __half* __restrict__ B,
                                          float* __restrict__ C,
                                          __half* __restrict__ C1,
                                          float scale)
{
    extern __shared__ char smraw[];
    const uint32_t s0 = smem_u32(smraw);

    const int tid  = threadIdx.x;
    const int warp = tid >> 5;
    const int lane = tid & 31;
    const int m0   = blockIdx.y * 128;
    const int n0   = blockIdx.x * 128;
    const int wm   = (warp >> 2) * 32;
    const int wn   = (warp & 3) * 32;

    const char* ga = (const char*)(A + (size_t)m0 * DDIM);
    const char* gb = (const char*)(B + (size_t)n0 * DDIM);
    const int lrow = tid >> 2, lc = tid & 3;
    const size_t goff = (size_t)lrow * 2048 + lc * 16;
    const uint32_t soff = (uint32_t)lrow * STRIDE + lc * 16;

#define LOAD_STAGE(kc, st)                                                     \
    {                                                                          \
        const uint32_t sb = s0 + (st) * STGB + soff;                           \
        const size_t go = goff + (kc) * 64;                                    \
        cp16(sb,       ga + go);                                               \
        cp16(sb + OPB, gb + go);                                               \
    }

    float acc[2][4][4];
#pragma unroll
    for (int i = 0; i < 2; i++)
#pragma unroll
        for (int j = 0; j < 4; j++)
#pragma unroll
            for (int r = 0; r < 4; r++) acc[i][j][r] = 0.f;

    LOAD_STAGE(0, 0); CP_COMMIT();
    LOAD_STAGE(1, 1); CP_COMMIT();

    const int arow_b = (lane & 15);
    const int ahalf  = (lane >> 4);

    for (int i = 0; i < 32; i++) {
        if (i < 30) { CP_WAIT(1); } else if (i == 30) { CP_WAIT(0); }
        __syncthreads();
        if (i < 30) { LOAD_STAGE(i + 2, (i + 2) % NSTG); CP_COMMIT(); }

        const uint32_t base = s0 + (i % NSTG) * STGB;
#pragma unroll
        for (int g = 0; g < 2; g++) {
            const uint32_t coff = (uint32_t)(2 * g + ahalf) * 16;
            uint32_t af[2][4], bf[4][2];
#pragma unroll
            for (int mi = 0; mi < 2; mi++) {
                const uint32_t ra = (uint32_t)(wm + mi * 16 + arow_b) * STRIDE + coff;
                LDSM_X4(af[mi][0], af[mi][1], af[mi][2], af[mi][3], base + ra);
            }
#pragma unroll
            for (int jp = 0; jp < 2; jp++) {
                const uint32_t rbo = (uint32_t)(wn + jp * 16 + arow_b) * STRIDE + coff;
                uint32_t t0, t1, t2, t3;
                LDSM_X4(t0, t1, t2, t3, base + OPB + rbo);
                bf[2 * jp][0] = t0; bf[2 * jp][1] = t2;
                bf[2 * jp + 1][0] = t1; bf[2 * jp + 1][1] = t3;
            }
#pragma unroll
            for (int mi = 0; mi < 2; mi++)
#pragma unroll
                for (int nj = 0; nj < 4; nj++)
                    mma16816(acc[mi][nj], af[mi], bf[nj]);
        }
    }

    const int crow = lane >> 2;
    const int ccol = (lane & 3) * 2;
#pragma unroll
    for (int mi = 0; mi < 2; mi++)
#pragma unroll
        for (int nj = 0; nj < 4; nj++) {
            const size_t r0 = (size_t)(m0 + wm + mi * 16 + crow) * DDIM + (n0 + wn + nj * 8 + ccol);
            if (MODE == 0) {
                *(float2*)(C + r0) = make_float2(acc[mi][nj][0], acc[mi][nj][1]);
                *(float2*)(C + r0 + 8 * DDIM) = make_float2(acc[mi][nj][2], acc[mi][nj][3]);
            } else {
                *(uint32_t*)(C1 + r0) = pack_h(acc[mi][nj][0] * scale, acc[mi][nj][1] * scale);
                *(uint32_t*)(C1 + r0 + 8 * DDIM) = pack_h(acc[mi][nj][2] * scale, acc[mi][nj][3] * scale);
            }
        }
#undef LOAD_STAGE
}

__global__ void __launch_bounds__(512, 1) qkv_tc_kernel()
{
    if (blockIdx.z == 0)                       // Q pre-scaled by 1/sqrt(64)
        hmma_gemm<2>(g_x, g_wq, nullptr, g_q, 0.125f);
    else if (blockIdx.z == 1)
        hmma_gemm<2>(g_x, g_wk, nullptr, g_k, 1.0f);
    else
        hmma_gemm<2>(g_x, g_wv, nullptr, g_v, 1.0f);
}

__global__ void __launch_bounds__(512, 1) out_tc_kernel(float* __restrict__ out)
{
    hmma_gemm<0>(g_att, g_wo, out, nullptr, 1.0f);
}

// ---------------------------------------------------------------------------
// conversions (single fp16)
// ---------------------------------------------------------------------------
__global__ void __launch_bounds__(256) cvt_x_kernel(const float4* __restrict__ src)
{
    int i = blockIdx.x * 256 + threadIdx.x;
    float4 v = src[i];
    ((uint32_t*)g_x)[2 * i]     = pack_h(v.x, v.y);
    ((uint32_t*)g_x)[2 * i + 1] = pack_h(v.z, v.w);
}

__global__ void __launch_bounds__(256) cvt_w_kernel(const float4* __restrict__ wk,
                                                    const float4* __restrict__ wq,
                                                    const float4* __restrict__ wv,
                                                    const float4* __restrict__ wo)
{
    int i = blockIdx.x * 256 + threadIdx.x;
    const float4* src;
    __half* dst;
    switch (blockIdx.z) {
        case 0:  src = wq; dst = g_wq; break;
        case 1:  src = wk; dst = g_wk; break;
        case 2:  src = wv; dst = g_wv; break;
        default: src = wo; dst = g_wo; break;
    }
    float4 v = src[i];
    ((uint32_t*)dst)[2 * i]     = pack_h(v.x, v.y);
    ((uint32_t*)dst)[2 * i + 1] = pack_h(v.z, v.w);
}

// ---------------------------------------------------------------------------
// Tensor-core causal flash attention, fp32 accum, single-term fp16 Q/K/V/P.
// CTA = 128 q-rows x one (b,h); 256 threads, 8 warps x 16 rows. KV tiles of
// 64 keys double-buffered cp.async. Scores pre-scaled (Q *= 0.125 in proj).
// Row stride 144B -> conflict-free ldmatrix.
// ---------------------------------------------------------------------------
#define AT_ROWB  144
#define AT_OP    9216              // 64 * 144
#define AT_STG   (2 * AT_OP)       // k, v
#define AT_SMEM  (2 * AT_STG)      // 36864 (covers Q staging 18432)

__global__ void __launch_bounds__(256, 2) attn_tc_kernel()
{
    extern __shared__ char smraw[];
    const uint32_t s0 = smem_u32(smraw);
    const int tid  = threadIdx.x;
    const int warp = tid >> 5;
    const int lane = tid & 31;
    const int y    = 7 - (int)blockIdx.x;      // heavy blocks first
    const int bh   = blockIdx.y;
    const int b    = bh >> 4, h = bh & 15;
    const int qb   = y * 128;
    const int nt   = 2 * y + 2;                // KV tiles of 64
    const size_t rb = (size_t)b * TDIM;

    // ---- stage Q 128x64 -> smem, then ldmatrix to regs ---------------------
    {
        const __half* src = g_q + (rb + qb) * DDIM + h * 64;
#pragma unroll
        for (int j = 0; j < 4; j++) {
            int id = tid + (j << 8);            // 0..1023
            int row = id >> 3, c = id & 7;
            cp16(s0 + row * AT_ROWB + c * 16, src + (size_t)row * DDIM + c * 8);
        }
        CP_COMMIT(); CP_WAIT(0);
        __syncthreads();
    }

    const int l15 = lane & 15, lh = lane >> 4;
    uint32_t qf[4][4];
#pragma unroll
    for (int ks = 0; ks < 4; ks++) {
        uint32_t ad = s0 + (uint32_t)(warp * 16 + l15) * AT_ROWB
                      + (uint32_t)(ks * 16 + lh * 8) * 2;
        LDSM_X4(qf[ks][0], qf[ks][1], qf[ks][2], qf[ks][3], ad);
    }
    __syncthreads();   // Q smem region free before KV loads reuse it

    float O[8][4], m[2], l[2];
    m[0] = m[1] = -1e30f;
    l[0] = l[1] = 0.f;
#pragma unroll
    for (int nj = 0; nj < 8; nj++)
#pragma unroll
        for (int c = 0; c < 4; c++) O[nj][c] = 0.f;

    const int crow = lane >> 2, ccol = (lane & 3) * 2;

#define KV_LOAD(t, st)                                                              \
    {                                                                               \
        const __half* kb_ = g_k + (rb + (t) * 64) * DDIM + h * 64;                  \
        const __half* vb_ = g_v + (rb + (t) * 64) * DDIM + h * 64;                  \
        const uint32_t ds = s0 + (st) * AT_STG;                                     \
        _Pragma("unroll")                                                           \
        for (int j = 0; j < 4; j++) {                                               \
            int id = tid + (j << 8);                                                \
            int tile = id >> 9;                                                     \
            int within = id & 511;                                                  \
            int row = within >> 3, c = within & 7;                                  \
            const __half* sc = tile ? vb_ : kb_;                                    \
            cp16(ds + tile * AT_OP + row * AT_ROWB + c * 16,                        \
                 sc + (size_t)row * DDIM + c * 8);                                  \
        }                                                                           \
    }

    KV_LOAD(0, 0); CP_COMMIT();
    KV_LOAD(1, 1); CP_COMMIT();

    const int koffV = (lane & 7) + (((lane >> 3) & 1) << 3);
    const int doffV = (lane >> 4) << 3;

    for (int t = 0; t < nt; t++) {
        CP_WAIT(1);
        __syncthreads();
        const uint32_t kb = s0 + (t & 1) * AT_STG;

        // ---- S = Q K^T ----------------------------------------------------
        float S[8][4];
#pragma unroll
        for (int nj = 0; nj < 8; nj++)
#pragma unroll
            for (int c = 0; c < 4; c++) S[nj][c] = 0.f;

#pragma unroll
        for (int ks = 0; ks < 4; ks++) {
#pragma unroll
            for (int nj2 = 0; nj2 < 4; nj2++) {
                const uint32_t ad = kb + (uint32_t)(nj2 * 16 + l15) * AT_ROWB
                                    + (uint32_t)(ks * 16 + lh * 8) * 2;
                uint32_t k0, k1, k2, k3;
                LDSM_X4(k0, k1, k2, k3, ad);
                uint32_t b0[2] = {k0, k2}, b1[2] = {k1, k3};
                mma16816(S[2 * nj2], qf[ks], b0);
                mma16816(S[2 * nj2 + 1], qf[ks], b1);
            }
        }

        // ---- online softmax -----------------------------------------------
        const bool masked = (t >= nt - 2);
        {
            const int row0 = qb + warp * 16 + crow;
            const int row1 = row0 + 8;
            if (masked) {
                const int colb = t * 64 + ccol;
#pragma unroll
                for (int nj = 0; nj < 8; nj++) {
                    const int c0 = colb + nj * 8;
                    if (c0 > row0)     S[nj][0] = -1e30f;
                    if (c0 + 1 > row0) S[nj][1] = -1e30f;
                    if (c0 > row1)     S[nj][2] = -1e30f;
                    if (c0 + 1 > row1) S[nj][3] = -1e30f;
                }
            }
            float mx0 = -1e30f, mx1 = -1e30f;
#pragma unroll
            for (int nj = 0; nj < 8; nj++) {
                mx0 = fmaxf(mx0, fmaxf(S[nj][0], S[nj][1]));
                mx1 = fmaxf(mx1, fmaxf(S[nj][2], S[nj][3]));
            }
            mx0 = fmaxf(mx0, __shfl_xor_sync(0xffffffff, mx0, 1));
            mx0 = fmaxf(mx0, __shfl_xor_sync(0xffffffff, mx0, 2));
            mx1 = fmaxf(mx1, __shfl_xor_sync(0xffffffff, mx1, 1));
            mx1 = fmaxf(mx1, __shfl_xor_sync(0xffffffff, mx1, 2));
            const float mn0 = fmaxf(m[0], mx0);
            const float mn1 = fmaxf(m[1], mx1);
            const float a0 = __expf(m[0] - mn0);
            const float a1 = __expf(m[1] - mn1);
            m[0] = mn0; m[1] = mn1;
            float rs0 = 0.f, rs1 = 0.f;
#pragma unroll
            for (int nj = 0; nj < 8; nj++) {
                S[nj][0] = __expf(S[nj][0] - mn0);
                S[nj][1] = __expf(S[nj][1] - mn0);
                S[nj][2] = __expf(S[nj][2] - mn1);
                S[nj][3] = __expf(S[nj][3] - mn1);
                rs0 += S[nj][0] + S[nj][1];
                rs1 += S[nj][2] + S[nj][3];
            }
            l[0] = l[0] * a0 + rs0;
            l[1] = l[1] * a1 + rs1;
#pragma unroll
            for (int nj = 0; nj < 8; nj++) {
                O[nj][0] *= a0; O[nj][1] *= a0;
                O[nj][2] *= a1; O[nj][3] *= a1;
            }
        }

        // ---- O += P V (single-term P) -------------------------------------
        const uint32_t vb = kb + AT_OP;
#pragma unroll
        for (int ks = 0; ks < 4; ks++) {
            uint32_t pf[4];
            {
                const float* sA = S[2 * ks];
                const float* sB = S[2 * ks + 1];
                pf[0] = pack_h(sA[0], sA[1]);
                pf[1] = pack_h(sA[2], sA[3]);
                pf[2] = pack_h(sB[0], sB[1]);
                pf[3] = pack_h(sB[2], sB[3]);
            }
#pragma unroll
            for (int nj2 = 0; nj2 < 4; nj2++) {
                const uint32_t ad = vb + (uint32_t)(ks * 16 + koffV) * AT_ROWB
                                    + (uint32_t)(nj2 * 16 + doffV) * 2;
                uint32_t v0, v1, v2, v3;
                LDSM_X4_T(v0, v1, v2, v3, ad);
                uint32_t vp0[2] = {v0, v1}, vp1[2] = {v2, v3};
                mma16816(O[2 * nj2], pf, vp0);
                mma16816(O[2 * nj2 + 1], pf, vp1);
            }
        }

        __syncthreads();                     // all warps done with stage t&1
        if (t + 2 < nt) KV_LOAD(t + 2, t & 1);
        CP_COMMIT();
    }

    // ---- epilogue: normalize, store single fp16 ---------------------------
    {
        float s0v = l[0], s1v = l[1];
        s0v += __shfl_xor_sync(0xffffffff, s0v, 1);
        s0v += __shfl_xor_sync(0xffffffff, s0v, 2);
        s1v += __shfl_xor_sync(0xffffffff, s1v, 1);
        s1v += __shfl_xor_sync(0xffffffff, s1v, 2);
        const float inv0 = 1.f / s0v, inv1 = 1.f / s1v;
        const int row0 = qb + warp * 16 + crow;
        const size_t a0 = (rb + row0) * DDIM + h * 64;
        const size_t a1 = a0 + 8 * DDIM;
#pragma unroll
        for (int nj = 0; nj < 8; nj++) {
            const int col = nj * 8 + ccol;
            *(uint32_t*)(g_att + a0 + col) = pack_h(O[nj][0] * inv0, O[nj][1] * inv0);
            *(uint32_t*)(g_att + a1 + col) = pack_h(O[nj][2] * inv1, O[nj][3] * inv1);
        }
    }
#undef KV_LOAD
}

// ---------------------------------------------------------------------------
// Inputs (metadata order): x, Wk, Wq, Wv, Wo. Output fp32 [8,1024,1024].
// ---------------------------------------------------------------------------
extern "C" void kernel_launch(void* const* d_in, const int* in_sizes, int n_in,
                              void* d_out, int out_size)
{
    const float* x  = (const float*)d_in[0];
    const float* Wk = (const float*)d_in[1];
    const float* Wq = (const float*)d_in[2];
    const float* Wv = (const float*)d_in[3];
    const float* Wo = (const float*)d_in[4];
    float* out = (float*)d_out;

    static int configured = 0;
    if (!configured) {
        cudaFuncSetAttribute(qkv_tc_kernel, cudaFuncAttributeMaxDynamicSharedMemorySize, SMEM_DYN);
        cudaFuncSetAttribute(out_tc_kernel, cudaFuncAttributeMaxDynamicSharedMemorySize, SMEM_DYN);
        cudaFuncSetAttribute(attn_tc_kernel, cudaFuncAttributeMaxDynamicSharedMemorySize, AT_SMEM);
        configured = 1;
    }

    cvt_x_kernel<<<8192, 256>>>((const float4*)x);
    cvt_w_kernel<<<dim3(1024, 1, 4), 256>>>((const float4*)Wk, (const float4*)Wq,
                                            (const float4*)Wv, (const float4*)Wo);

    qkv_tc_kernel<<<dim3(8, 64, 3), 512, SMEM_DYN>>>();

    attn_tc_kernel<<<dim3(8, 128), 256, AT_SMEM>>>();

    out_tc_kernel<<<dim3(8, 64), 512, SMEM_DYN>>>(out);
}